// round 2
// baseline (speedup 1.0000x reference)
#include <cuda_runtime.h>
#include <cstdint>

#define NN 100000
#define EMAX 1600000

// -------- scratch (static device globals; no runtime allocation) --------
__device__ __align__(16) int   g_pos32[2 * EMAX];
__device__ __align__(16) int   g_neg32[2 * EMAX];
__device__ __align__(16) int   g_csr[EMAX];        // neighbor col ids grouped by row
__device__ __align__(16) int   g_ideg[NN];
__device__ __align__(16) int   g_offs[NN + 1];
__device__ __align__(16) int   g_cursor[NN];
__device__ __align__(16) float g_dis[NN];
__device__ __align__(16) float g_h[NN * 64];       // dis[i]*(x@W1+b1)
__device__ __align__(16) float g_acc1[NN * 64];    // relu(layer1 out)
__device__ __align__(16) float g_t[NN * 64];       // dis[i]*(acc1@W2+b2)
__device__ __align__(16) float g_acc2[NN * 64];    // z
__device__ int g_is64;

// -------- dtype-agnostic index load (int32 vs int64, decided at runtime) ----
__device__ __forceinline__ long long ldidx(const void* p, long long i) {
    if (g_is64) return ((const long long*)p)[i];
    return (long long)((const int*)p)[i];
}

// Detect whether edge indices are int64 (odd 32-bit words all zero, since
// node ids < 2^17) or int32 (odd words are random node ids).
__global__ void detect_kernel(const unsigned int* p) {
    __shared__ int ok;
    if (threadIdx.x == 0) ok = 1;
    __syncthreads();
    if (p[2 * threadIdx.x + 1] != 0u) atomicExch(&ok, 0);
    __syncthreads();
    if (threadIdx.x == 0) g_is64 = ok;
}

// Convert indices to int32 once.
__global__ void conv_kernel(const void* src, int* dst, long long n) {
    long long i = (long long)blockIdx.x * blockDim.x + threadIdx.x;
    if (i < n) dst[i] = (int)ldidx(src, i);
}

__global__ void zeroi_kernel(int* p, int n) {
    int i = blockIdx.x * blockDim.x + threadIdx.x;
    if (i < n) p[i] = 0;
}

__global__ void degi_kernel(const int* __restrict__ pos, long long E, int* ideg) {
    long long e = (long long)blockIdx.x * blockDim.x + threadIdx.x;
    if (e < E) atomicAdd(&ideg[pos[e]], 1);
}

// Single-block exclusive scan over n=100k degrees; writes offs[0..n] and cursor.
__global__ void scan_kernel(const int* __restrict__ ideg, int* offs, int* cursor, int n) {
    __shared__ int part[1024];
    int tid = threadIdx.x;
    int per = (n + 1023) / 1024;
    int start = tid * per;
    int end = min(start + per, n);
    int s = 0;
    for (int i = start; i < end; i++) s += ideg[i];
    part[tid] = s;
    __syncthreads();
    for (int off = 1; off < 1024; off <<= 1) {
        int t2 = (tid >= off) ? part[tid - off] : 0;
        __syncthreads();
        part[tid] += t2;
        __syncthreads();
    }
    int run = part[tid] - s;   // exclusive base
    for (int i = start; i < end; i++) {
        offs[i] = run;
        cursor[i] = run;
        run += ideg[i];
    }
    if (tid == 0) offs[n] = part[1023];
}

__global__ void fill_kernel(const int* __restrict__ pos, long long E,
                            int* cursor, int* csr) {
    long long e = (long long)blockIdx.x * blockDim.x + threadIdx.x;
    if (e >= E) return;
    int row = pos[e];
    int col = pos[E + e];
    int slot = atomicAdd(&cursor[row], 1);
    csr[slot] = col;
}

__global__ void dis_kernel(const int* __restrict__ ideg, float* dis, int n) {
    int i = blockIdx.x * blockDim.x + threadIdx.x;
    if (i >= n) return;
    int d = ideg[i];
    dis[i] = (d > 0) ? rsqrtf((float)d) : 0.0f;
}

// Y[row,:] = dis[row] * (X[row,:] @ W + b).  256 threads/block, 64 rows/block.
__global__ void gemm_kernel(const float* __restrict__ X,
                            const float* __restrict__ W,
                            const float* __restrict__ bias,
                            const float* __restrict__ dis,
                            float* __restrict__ Y,
                            int n, int K) {
    __shared__ float Ws[32 * 64];
    __shared__ float xs[64 * 36];

    int tid = threadIdx.x;
    int r = tid >> 2;
    int cq = (tid & 3) * 16;
    long long row0 = (long long)blockIdx.x * 64;

    float acc[16];
#pragma unroll
    for (int j = 0; j < 16; j++) acc[j] = 0.0f;

    for (int kt = 0; kt < K; kt += 32) {
        const float4* Wv = (const float4*)(W + (long long)kt * 64);
        float4* Wsv = (float4*)Ws;
        Wsv[tid] = Wv[tid];
        Wsv[tid + 256] = Wv[tid + 256];
#pragma unroll
        for (int rep = 0; rep < 2; rep++) {
            int idx = tid + rep * 256;
            int rr = idx >> 3;
            int kk4 = idx & 7;
            long long row = row0 + rr;
            float4 v = make_float4(0.f, 0.f, 0.f, 0.f);
            if (row < n)
                v = *(const float4*)(X + row * K + kt + kk4 * 4);
            *(float4*)(xs + rr * 36 + kk4 * 4) = v;
        }
        __syncthreads();

#pragma unroll
        for (int k = 0; k < 32; k++) {
            float xv = xs[r * 36 + k];
            const float4* wr = (const float4*)(Ws + k * 64 + cq);
            float4 w0 = wr[0], w1 = wr[1], w2 = wr[2], w3 = wr[3];
            acc[0]  += xv * w0.x;  acc[1]  += xv * w0.y;
            acc[2]  += xv * w0.z;  acc[3]  += xv * w0.w;
            acc[4]  += xv * w1.x;  acc[5]  += xv * w1.y;
            acc[6]  += xv * w1.z;  acc[7]  += xv * w1.w;
            acc[8]  += xv * w2.x;  acc[9]  += xv * w2.y;
            acc[10] += xv * w2.z;  acc[11] += xv * w2.w;
            acc[12] += xv * w3.x;  acc[13] += xv * w3.y;
            acc[14] += xv * w3.z;  acc[15] += xv * w3.w;
        }
        __syncthreads();
    }

    long long row = row0 + r;
    if (row < n) {
        float dr = dis[row];
        float* yp = Y + row * 64 + cq;
#pragma unroll
        for (int q = 0; q < 4; q++) {
            float4 o;
            o.x = (acc[q * 4 + 0] + bias[cq + q * 4 + 0]) * dr;
            o.y = (acc[q * 4 + 1] + bias[cq + q * 4 + 1]) * dr;
            o.z = (acc[q * 4 + 2] + bias[cq + q * 4 + 2]) * dr;
            o.w = (acc[q * 4 + 3] + bias[cq + q * 4 + 3]) * dr;
            *(float4*)(yp + q * 4) = o;
        }
    }
}

// Warp-per-node gather: out[row,:] = act( dis[row] * sum_{col in CSR[row]} H[col,:] )
__global__ void gather_kernel(const int* __restrict__ offs,
                              const int* __restrict__ csr,
                              const float* __restrict__ dis,
                              const float* __restrict__ H,
                              float* __restrict__ out,
                              int n, int do_relu) {
    int warp = (int)(((long long)blockIdx.x * blockDim.x + threadIdx.x) >> 5);
    if (warp >= n) return;
    int lane = threadIdx.x & 31;
    int s = offs[warp];
    int e = offs[warp + 1];
    float2 acc = make_float2(0.f, 0.f);
    for (int j = s; j < e; j += 32) {
        int cnt = min(32, e - j);
        int c = (lane < cnt) ? csr[j + lane] : 0;
#pragma unroll 4
        for (int k = 0; k < cnt; k++) {
            int col = __shfl_sync(0xffffffffu, c, k);
            float2 v = __ldg(((const float2*)H) + (long long)col * 32 + lane);
            acc.x += v.x;
            acc.y += v.y;
        }
    }
    float dr = dis[warp];
    acc.x *= dr;
    acc.y *= dr;
    if (do_relu) {
        acc.x = fmaxf(acc.x, 0.f);
        acc.y = fmaxf(acc.y, 0.f);
    }
    ((float2*)out)[(long long)warp * 32 + lane] = acc;
}

// Decode: one warp per output edge. out[e] = dot(z[a], z[b]) over 64 dims.
__global__ void decode_kernel(const int* __restrict__ pos,
                              const int* __restrict__ neg, long long E,
                              const float* __restrict__ Z, float* __restrict__ out) {
    long long w = ((long long)blockIdx.x * blockDim.x + threadIdx.x) >> 5;
    if (w >= 2 * E) return;
    int lane = threadIdx.x & 31;

    int a = 0, b = 0;
    if (lane == 0) {
        if (w < E) { a = pos[w];      b = pos[E + w]; }
        else       { long long e = w - E;
                     a = neg[e];      b = neg[E + e]; }
    }
    a = __shfl_sync(0xffffffffu, a, 0);
    b = __shfl_sync(0xffffffffu, b, 0);

    float2 za = __ldg(((const float2*)Z) + (long long)a * 32 + lane);
    float2 zb = __ldg(((const float2*)Z) + (long long)b * 32 + lane);
    float s = za.x * zb.x + za.y * zb.y;
#pragma unroll
    for (int off = 16; off; off >>= 1)
        s += __shfl_xor_sync(0xffffffffu, s, off);
    if (lane == 0) out[w] = s;
}

extern "C" void kernel_launch(void* const* d_in, const int* in_sizes, int n_in,
                              void* d_out, int out_size) {
    const float* x   = (const float*)d_in[0];
    const void*  pos = d_in[1];
    const void*  neg = d_in[2];
    const float* W1  = (const float*)d_in[3];
    const float* b1  = (const float*)d_in[4];
    const float* W2  = (const float*)d_in[5];
    const float* b2  = (const float*)d_in[6];
    float* out = (float*)d_out;

    long long E = (long long)in_sizes[1] / 2;   // 1.6M
    int n = NN;
    int Fin = in_sizes[0] / n;                  // 256

    int *pos32, *neg32, *csr, *ideg, *offs, *cursor;
    float *dis, *h, *acc1, *t, *acc2;
    cudaGetSymbolAddress((void**)&pos32,  g_pos32);
    cudaGetSymbolAddress((void**)&neg32,  g_neg32);
    cudaGetSymbolAddress((void**)&csr,    g_csr);
    cudaGetSymbolAddress((void**)&ideg,   g_ideg);
    cudaGetSymbolAddress((void**)&offs,   g_offs);
    cudaGetSymbolAddress((void**)&cursor, g_cursor);
    cudaGetSymbolAddress((void**)&dis,    g_dis);
    cudaGetSymbolAddress((void**)&h,      g_h);
    cudaGetSymbolAddress((void**)&acc1,   g_acc1);
    cudaGetSymbolAddress((void**)&t,      g_t);
    cudaGetSymbolAddress((void**)&acc2,   g_acc2);

    detect_kernel<<<1, 64>>>((const unsigned int*)pos);

    long long twoE = 2 * E;
    int cblocks = (int)((twoE + 255) / 256);
    conv_kernel<<<cblocks, 256>>>(pos, pos32, twoE);
    conv_kernel<<<cblocks, 256>>>(neg, neg32, twoE);

    zeroi_kernel<<<(n + 255) / 256, 256>>>(ideg, n);
    int eblocks = (int)((E + 255) / 256);
    degi_kernel<<<eblocks, 256>>>(pos32, E, ideg);
    scan_kernel<<<1, 1024>>>(ideg, offs, cursor, n);
    fill_kernel<<<eblocks, 256>>>(pos32, E, cursor, csr);
    dis_kernel<<<(n + 255) / 256, 256>>>(ideg, dis, n);

    int gblocks = (n + 63) / 64;
    gemm_kernel<<<gblocks, 256>>>(x, W1, b1, dis, h, n, Fin);

    int wblocks = (n * 32 + 255) / 256;
    gather_kernel<<<wblocks, 256>>>(offs, csr, dis, h, acc1, n, 1);

    gemm_kernel<<<gblocks, 256>>>(acc1, W2, b2, dis, t, n, 64);
    gather_kernel<<<wblocks, 256>>>(offs, csr, dis, t, acc2, n, 0);

    int dblocks = (int)((2 * E * 32 + 255) / 256);
    decode_kernel<<<dblocks, 256>>>(pos32, neg32, E, acc2, out);
}

// round 3
// speedup vs baseline: 1.0623x; 1.0623x over previous
#include <cuda_runtime.h>
#include <cstdint>

#define NN 100000
#define EMAX 1600000
#define GS_BLOCKS 2368          // 16 CTAs/SM * 148 SMs
#define GS_THREADS 256

// -------- scratch (static device globals; no runtime allocation) --------
__device__ __align__(16) int   g_pos32[2 * EMAX];
__device__ __align__(16) int   g_neg32[2 * EMAX];
__device__ __align__(16) int   g_csr[EMAX];        // neighbor col ids grouped by row
__device__ __align__(16) int   g_ideg[NN];         // zero-initialized at load; decode re-zeros
__device__ __align__(16) int   g_offs[NN + 1];
__device__ __align__(16) int   g_cursor[NN];
__device__ __align__(16) float g_dis[NN];
__device__ __align__(16) float g_h[NN * 64];       // dis[i]*(x@W1+b1)
__device__ __align__(16) float g_acc1[NN * 64];    // relu(layer1 aggregated)
__device__ __align__(16) float g_t[NN * 64];       // dis[i]*(acc1@W2+b2)
__device__ __align__(16) float g_acc2[NN * 64];    // z
__device__ int g_is64;

// -------- dtype-agnostic index load (int32 vs int64, decided at runtime) ----
__device__ __forceinline__ long long ldidx(const void* p, long long i) {
    if (g_is64) return ((const long long*)p)[i];
    return (long long)((const int*)p)[i];
}

// Detect int64 vs int32 indices (odd 32-bit words all zero => int64, since ids < 2^17).
__global__ void detect_kernel(const unsigned int* p) {
    __shared__ int ok;
    if (threadIdx.x == 0) ok = 1;
    __syncthreads();
    if (p[2 * threadIdx.x + 1] != 0u) atomicExch(&ok, 0);
    __syncthreads();
    if (threadIdx.x == 0) g_is64 = ok;
}

// Convert both index arrays to int32 and count row degrees, one pass, grid-stride.
// g_ideg must be zero on entry (static init first run; decode tail thereafter).
__global__ void convdeg_kernel(const void* __restrict__ pos,
                               const void* __restrict__ neg,
                               int* __restrict__ pos32, int* __restrict__ neg32,
                               int* __restrict__ ideg, long long twoE) {
    long long E = twoE >> 1;
    long long stride = (long long)gridDim.x * blockDim.x;
    for (long long i = (long long)blockIdx.x * blockDim.x + threadIdx.x;
         i < twoE; i += stride) {
        int pv = (int)ldidx(pos, i);
        pos32[i] = pv;
        neg32[i] = (int)ldidx(neg, i);
        if (i < E) atomicAdd(&ideg[pv], 1);
    }
}

// Single-block exclusive scan over n=100k degrees; writes offs[0..n], cursor, dis.
__global__ void scan_kernel(const int* __restrict__ ideg, int* offs, int* cursor,
                            float* dis, int n) {
    __shared__ int part[1024];
    int tid = threadIdx.x;
    int per = (n + 1023) / 1024;
    int start = tid * per;
    int end = min(start + per, n);
    int s = 0;
    for (int i = start; i < end; i++) s += ideg[i];
    part[tid] = s;
    __syncthreads();
    for (int off = 1; off < 1024; off <<= 1) {
        int t2 = (tid >= off) ? part[tid - off] : 0;
        __syncthreads();
        part[tid] += t2;
        __syncthreads();
    }
    int run = part[tid] - s;   // exclusive base
    for (int i = start; i < end; i++) {
        int d = ideg[i];
        offs[i] = run;
        cursor[i] = run;
        dis[i] = (d > 0) ? rsqrtf((float)d) : 0.0f;
        run += d;
    }
    if (tid == 0) offs[n] = part[1023];
}

__global__ void fill_kernel(const int* __restrict__ pos, long long E,
                            int* cursor, int* csr) {
    long long stride = (long long)gridDim.x * blockDim.x;
    for (long long e = (long long)blockIdx.x * blockDim.x + threadIdx.x;
         e < E; e += stride) {
        int row = pos[e];
        int col = pos[E + e];
        int slot = atomicAdd(&cursor[row], 1);
        csr[slot] = col;
    }
}

// Y[row,:] = dis[row] * (X[row,:] @ W + b).  256 threads/block, 64 rows/block.
__global__ void gemm_kernel(const float* __restrict__ X,
                            const float* __restrict__ W,
                            const float* __restrict__ bias,
                            const float* __restrict__ dis,
                            float* __restrict__ Y,
                            int n, int K) {
    __shared__ float Ws[32 * 64];
    __shared__ float xs[64 * 36];

    int tid = threadIdx.x;
    int r = tid >> 2;
    int cq = (tid & 3) * 16;
    long long row0 = (long long)blockIdx.x * 64;

    float acc[16];
#pragma unroll
    for (int j = 0; j < 16; j++) acc[j] = 0.0f;

    for (int kt = 0; kt < K; kt += 32) {
        const float4* Wv = (const float4*)(W + (long long)kt * 64);
        float4* Wsv = (float4*)Ws;
        Wsv[tid] = Wv[tid];
        Wsv[tid + 256] = Wv[tid + 256];
#pragma unroll
        for (int rep = 0; rep < 2; rep++) {
            int idx = tid + rep * 256;
            int rr = idx >> 3;
            int kk4 = idx & 7;
            long long row = row0 + rr;
            float4 v = make_float4(0.f, 0.f, 0.f, 0.f);
            if (row < n)
                v = *(const float4*)(X + row * K + kt + kk4 * 4);
            *(float4*)(xs + rr * 36 + kk4 * 4) = v;
        }
        __syncthreads();

#pragma unroll
        for (int k = 0; k < 32; k++) {
            float xv = xs[r * 36 + k];
            const float4* wr = (const float4*)(Ws + k * 64 + cq);
            float4 w0 = wr[0], w1 = wr[1], w2 = wr[2], w3 = wr[3];
            acc[0]  += xv * w0.x;  acc[1]  += xv * w0.y;
            acc[2]  += xv * w0.z;  acc[3]  += xv * w0.w;
            acc[4]  += xv * w1.x;  acc[5]  += xv * w1.y;
            acc[6]  += xv * w1.z;  acc[7]  += xv * w1.w;
            acc[8]  += xv * w2.x;  acc[9]  += xv * w2.y;
            acc[10] += xv * w2.z;  acc[11] += xv * w2.w;
            acc[12] += xv * w3.x;  acc[13] += xv * w3.y;
            acc[14] += xv * w3.z;  acc[15] += xv * w3.w;
        }
        __syncthreads();
    }

    long long row = row0 + r;
    if (row < n) {
        float dr = dis[row];
        float* yp = Y + row * 64 + cq;
#pragma unroll
        for (int q = 0; q < 4; q++) {
            float4 o;
            o.x = (acc[q * 4 + 0] + bias[cq + q * 4 + 0]) * dr;
            o.y = (acc[q * 4 + 1] + bias[cq + q * 4 + 1]) * dr;
            o.z = (acc[q * 4 + 2] + bias[cq + q * 4 + 2]) * dr;
            o.w = (acc[q * 4 + 3] + bias[cq + q * 4 + 3]) * dr;
            *(float4*)(yp + q * 4) = o;
        }
    }
}

// Warp-per-node gather, grid-stride over nodes:
// out[row,:] = act( dis[row] * sum_{col in CSR[row]} H[col,:] )
__global__ void gather_kernel(const int* __restrict__ offs,
                              const int* __restrict__ csr,
                              const float* __restrict__ dis,
                              const float* __restrict__ H,
                              float* __restrict__ out,
                              int n, int do_relu) {
    int lane = threadIdx.x & 31;
    long long warp0 = ((long long)blockIdx.x * blockDim.x + threadIdx.x) >> 5;
    long long nwarps = ((long long)gridDim.x * blockDim.x) >> 5;

    for (long long node = warp0; node < n; node += nwarps) {
        int s = offs[node];
        int e = offs[node + 1];
        float2 acc = make_float2(0.f, 0.f);
        for (int j = s; j < e; j += 32) {
            int cnt = min(32, e - j);
            int c = (lane < cnt) ? csr[j + lane] : 0;
#pragma unroll 4
            for (int k = 0; k < cnt; k++) {
                int col = __shfl_sync(0xffffffffu, c, k);
                float2 v = __ldg(((const float2*)H) + (long long)col * 32 + lane);
                acc.x += v.x;
                acc.y += v.y;
            }
        }
        float dr = dis[node];
        acc.x *= dr;
        acc.y *= dr;
        if (do_relu) {
            acc.x = fmaxf(acc.x, 0.f);
            acc.y = fmaxf(acc.y, 0.f);
        }
        ((float2*)out)[node * 32 + lane] = acc;
    }
}

// Decode, grid-stride: one warp per output edge, out[e] = dot(z[a], z[b]).
// Tail duty: re-zero g_ideg for the next replay (deterministic state machine).
__global__ void decode_kernel(const int* __restrict__ pos,
                              const int* __restrict__ neg, long long E,
                              const float* __restrict__ Z, float* __restrict__ out,
                              int* __restrict__ ideg, int n) {
    long long tid = (long long)blockIdx.x * blockDim.x + threadIdx.x;
    if (tid < n) ideg[tid] = 0;     // reset degrees for next replay

    int lane = threadIdx.x & 31;
    long long warp0 = tid >> 5;
    long long nwarps = ((long long)gridDim.x * blockDim.x) >> 5;
    long long twoE = 2 * E;

    for (long long w = warp0; w < twoE; w += nwarps) {
        int a = 0, b = 0;
        if (lane == 0) {
            if (w < E) { a = pos[w];          b = pos[E + w]; }
            else       { long long e = w - E;
                         a = neg[e];          b = neg[E + e]; }
        }
        a = __shfl_sync(0xffffffffu, a, 0);
        b = __shfl_sync(0xffffffffu, b, 0);

        float2 za = __ldg(((const float2*)Z) + (long long)a * 32 + lane);
        float2 zb = __ldg(((const float2*)Z) + (long long)b * 32 + lane);
        float s = za.x * zb.x + za.y * zb.y;
#pragma unroll
        for (int off = 16; off; off >>= 1)
            s += __shfl_xor_sync(0xffffffffu, s, off);
        if (lane == 0) out[w] = s;
    }
}

extern "C" void kernel_launch(void* const* d_in, const int* in_sizes, int n_in,
                              void* d_out, int out_size) {
    const float* x   = (const float*)d_in[0];
    const void*  pos = d_in[1];
    const void*  neg = d_in[2];
    const float* W1  = (const float*)d_in[3];
    const float* b1  = (const float*)d_in[4];
    const float* W2  = (const float*)d_in[5];
    const float* b2  = (const float*)d_in[6];
    float* out = (float*)d_out;

    long long E = (long long)in_sizes[1] / 2;   // 1.6M
    int n = NN;
    int Fin = in_sizes[0] / n;                  // 256

    int *pos32, *neg32, *csr, *ideg, *offs, *cursor;
    float *dis, *h, *acc1, *t, *acc2;
    cudaGetSymbolAddress((void**)&pos32,  g_pos32);
    cudaGetSymbolAddress((void**)&neg32,  g_neg32);
    cudaGetSymbolAddress((void**)&csr,    g_csr);
    cudaGetSymbolAddress((void**)&ideg,   g_ideg);
    cudaGetSymbolAddress((void**)&offs,   g_offs);
    cudaGetSymbolAddress((void**)&cursor, g_cursor);
    cudaGetSymbolAddress((void**)&dis,    g_dis);
    cudaGetSymbolAddress((void**)&h,      g_h);
    cudaGetSymbolAddress((void**)&acc1,   g_acc1);
    cudaGetSymbolAddress((void**)&t,      g_t);
    cudaGetSymbolAddress((void**)&acc2,   g_acc2);

    detect_kernel<<<1, 64>>>((const unsigned int*)pos);

    convdeg_kernel<<<GS_BLOCKS, GS_THREADS>>>(pos, neg, pos32, neg32, ideg, 2 * E);
    scan_kernel<<<1, 1024>>>(ideg, offs, cursor, dis, n);
    fill_kernel<<<GS_BLOCKS, GS_THREADS>>>(pos32, E, cursor, csr);

    int gblocks = (n + 63) / 64;
    gemm_kernel<<<gblocks, 256>>>(x, W1, b1, dis, h, n, Fin);
    gather_kernel<<<GS_BLOCKS, GS_THREADS>>>(offs, csr, dis, h, acc1, n, 1);
    gemm_kernel<<<gblocks, 256>>>(acc1, W2, b2, dis, t, n, 64);
    gather_kernel<<<GS_BLOCKS, GS_THREADS>>>(offs, csr, dis, t, acc2, n, 0);

    decode_kernel<<<GS_BLOCKS, GS_THREADS>>>(pos32, neg32, E, acc2, out, ideg, n);
}

// round 4
// speedup vs baseline: 1.2443x; 1.1713x over previous
#include <cuda_runtime.h>
#include <cstdint>

#define NN 100000
#define EMAX 1600000
#define GS_BLOCKS 2368          // 16 CTAs/SM * 148 SMs
#define GS_THREADS 256

// -------- scratch (static device globals; no runtime allocation) --------
__device__ __align__(16) int   g_pos32[2 * EMAX];
__device__ __align__(16) int   g_neg32[2 * EMAX];
__device__ __align__(16) int   g_csr[EMAX];        // neighbor col ids grouped by row
__device__ __align__(16) int   g_ideg[NN];         // zero-initialized at load; decode re-zeros
__device__ __align__(16) int   g_offs[NN + 1];
__device__ __align__(16) int   g_cursor[NN];
__device__ __align__(16) float g_dis[NN];
__device__ __align__(16) float g_h[NN * 64];       // dis[i]*(x@W1+b1)
__device__ __align__(16) float g_acc1[NN * 64];    // relu(layer1 aggregated)
__device__ __align__(16) float g_t[NN * 64];       // dis[i]*(acc1@W2+b2)
__device__ __align__(16) float g_acc2[NN * 64];    // z
__device__ int g_is64;

// -------- dtype-agnostic index load (int32 vs int64, decided at runtime) ----
__device__ __forceinline__ long long ldidx(const void* p, long long i) {
    if (g_is64) return ((const long long*)p)[i];
    return (long long)((const int*)p)[i];
}

// Detect int64 vs int32 indices (odd 32-bit words all zero => int64, since ids < 2^17).
__global__ void detect_kernel(const unsigned int* p) {
    __shared__ int ok;
    if (threadIdx.x == 0) ok = 1;
    __syncthreads();
    if (p[2 * threadIdx.x + 1] != 0u) atomicExch(&ok, 0);
    __syncthreads();
    if (threadIdx.x == 0) g_is64 = ok;
}

// Convert both index arrays to int32 and count row degrees, one pass, grid-stride.
// g_ideg must be zero on entry (static init first run; decode tail thereafter).
__global__ void convdeg_kernel(const void* __restrict__ pos,
                               const void* __restrict__ neg,
                               int* __restrict__ pos32, int* __restrict__ neg32,
                               int* __restrict__ ideg, long long twoE) {
    long long E = twoE >> 1;
    long long stride = (long long)gridDim.x * blockDim.x;
    for (long long i = (long long)blockIdx.x * blockDim.x + threadIdx.x;
         i < twoE; i += stride) {
        int pv = (int)ldidx(pos, i);
        pos32[i] = pv;
        neg32[i] = (int)ldidx(neg, i);
        if (i < E) atomicAdd(&ideg[pv], 1);
    }
}

// Single-block exclusive scan over n=100k degrees; writes offs[0..n], cursor, dis.
__global__ void scan_kernel(const int* __restrict__ ideg, int* offs, int* cursor,
                            float* dis, int n) {
    __shared__ int part[1024];
    int tid = threadIdx.x;
    int per = (n + 1023) / 1024;
    int start = tid * per;
    int end = min(start + per, n);
    int s = 0;
    for (int i = start; i < end; i++) s += ideg[i];
    part[tid] = s;
    __syncthreads();
    for (int off = 1; off < 1024; off <<= 1) {
        int t2 = (tid >= off) ? part[tid - off] : 0;
        __syncthreads();
        part[tid] += t2;
        __syncthreads();
    }
    int run = part[tid] - s;   // exclusive base
    for (int i = start; i < end; i++) {
        int d = ideg[i];
        offs[i] = run;
        cursor[i] = run;
        dis[i] = (d > 0) ? rsqrtf((float)d) : 0.0f;
        run += d;
    }
    if (tid == 0) offs[n] = part[1023];
}

__global__ void fill_kernel(const int* __restrict__ pos, long long E,
                            int* cursor, int* csr) {
    long long stride = (long long)gridDim.x * blockDim.x;
    for (long long e = (long long)blockIdx.x * blockDim.x + threadIdx.x;
         e < E; e += stride) {
        int row = pos[e];
        int col = pos[E + e];
        int slot = atomicAdd(&cursor[row], 1);
        csr[slot] = col;
    }
}

// Y[row,:] = dis[row] * (X[row,:] @ W + b).  256 threads/block, 64 rows/block.
__global__ void gemm_kernel(const float* __restrict__ X,
                            const float* __restrict__ W,
                            const float* __restrict__ bias,
                            const float* __restrict__ dis,
                            float* __restrict__ Y,
                            int n, int K) {
    __shared__ float Ws[32 * 64];
    __shared__ float xs[64 * 36];

    int tid = threadIdx.x;
    int r = tid >> 2;
    int cq = (tid & 3) * 16;
    long long row0 = (long long)blockIdx.x * 64;

    float acc[16];
#pragma unroll
    for (int j = 0; j < 16; j++) acc[j] = 0.0f;

    for (int kt = 0; kt < K; kt += 32) {
        const float4* Wv = (const float4*)(W + (long long)kt * 64);
        float4* Wsv = (float4*)Ws;
        Wsv[tid] = Wv[tid];
        Wsv[tid + 256] = Wv[tid + 256];
#pragma unroll
        for (int rep = 0; rep < 2; rep++) {
            int idx = tid + rep * 256;
            int rr = idx >> 3;
            int kk4 = idx & 7;
            long long row = row0 + rr;
            float4 v = make_float4(0.f, 0.f, 0.f, 0.f);
            if (row < n)
                v = *(const float4*)(X + row * K + kt + kk4 * 4);
            *(float4*)(xs + rr * 36 + kk4 * 4) = v;
        }
        __syncthreads();

#pragma unroll
        for (int k = 0; k < 32; k++) {
            float xv = xs[r * 36 + k];
            const float4* wr = (const float4*)(Ws + k * 64 + cq);
            float4 w0 = wr[0], w1 = wr[1], w2 = wr[2], w3 = wr[3];
            acc[0]  += xv * w0.x;  acc[1]  += xv * w0.y;
            acc[2]  += xv * w0.z;  acc[3]  += xv * w0.w;
            acc[4]  += xv * w1.x;  acc[5]  += xv * w1.y;
            acc[6]  += xv * w1.z;  acc[7]  += xv * w1.w;
            acc[8]  += xv * w2.x;  acc[9]  += xv * w2.y;
            acc[10] += xv * w2.z;  acc[11] += xv * w2.w;
            acc[12] += xv * w3.x;  acc[13] += xv * w3.y;
            acc[14] += xv * w3.z;  acc[15] += xv * w3.w;
        }
        __syncthreads();
    }

    long long row = row0 + r;
    if (row < n) {
        float dr = dis[row];
        float* yp = Y + row * 64 + cq;
#pragma unroll
        for (int q = 0; q < 4; q++) {
            float4 o;
            o.x = (acc[q * 4 + 0] + bias[cq + q * 4 + 0]) * dr;
            o.y = (acc[q * 4 + 1] + bias[cq + q * 4 + 1]) * dr;
            o.z = (acc[q * 4 + 2] + bias[cq + q * 4 + 2]) * dr;
            o.w = (acc[q * 4 + 3] + bias[cq + q * 4 + 3]) * dr;
            *(float4*)(yp + q * 4) = o;
        }
    }
}

// Gather v2: warp per node, half-warp per neighbor, float4 lanes.
// lanes 0-15 accumulate even-position neighbors, 16-31 odd; combine at end.
// out[row,:] = act( dis[row] * sum_{col in CSR[row]} H[col,:] )
__global__ void gather_kernel(const int* __restrict__ offs,
                              const int* __restrict__ csr,
                              const float* __restrict__ dis,
                              const float* __restrict__ H,
                              float* __restrict__ out,
                              int n, int do_relu) {
    int lane = threadIdx.x & 31;
    int half = lane >> 4;        // 0 or 1
    int j = lane & 15;           // float4 slot within the 64-float row
    long long warp0 = ((long long)blockIdx.x * blockDim.x + threadIdx.x) >> 5;
    long long nwarps = ((long long)gridDim.x * blockDim.x) >> 5;
    const float4* H4 = (const float4*)H;

    for (long long node = warp0; node < n; node += nwarps) {
        int s = offs[node];
        int e = offs[node + 1];
        float4 acc = make_float4(0.f, 0.f, 0.f, 0.f);

        int base = s;
        // main loop: 4 neighbors per iteration (2 per half-warp), MLP=2/lane
        for (; base + 4 <= e; base += 4) {
            int c0 = csr[base + half];
            int c1 = csr[base + 2 + half];
            float4 v0 = H4[(long long)c0 * 16 + j];
            float4 v1 = H4[(long long)c1 * 16 + j];
            acc.x += v0.x + v1.x;
            acc.y += v0.y + v1.y;
            acc.z += v0.z + v1.z;
            acc.w += v0.w + v1.w;
        }
        // tail: up to 3 neighbors
        for (; base < e; base += 2) {
            int my = base + half;
            if (my < e) {
                int c = csr[my];
                float4 v = H4[(long long)c * 16 + j];
                acc.x += v.x; acc.y += v.y; acc.z += v.z; acc.w += v.w;
            }
        }

        // combine the two halves (lane j += lane j+16)
        acc.x += __shfl_xor_sync(0xffffffffu, acc.x, 16);
        acc.y += __shfl_xor_sync(0xffffffffu, acc.y, 16);
        acc.z += __shfl_xor_sync(0xffffffffu, acc.z, 16);
        acc.w += __shfl_xor_sync(0xffffffffu, acc.w, 16);

        if (half == 0) {
            float dr = dis[node];
            acc.x *= dr; acc.y *= dr; acc.z *= dr; acc.w *= dr;
            if (do_relu) {
                acc.x = fmaxf(acc.x, 0.f);
                acc.y = fmaxf(acc.y, 0.f);
                acc.z = fmaxf(acc.z, 0.f);
                acc.w = fmaxf(acc.w, 0.f);
            }
            ((float4*)out)[node * 16 + j] = acc;
        }
    }
}

// Decode v2: 8 lanes per edge (warp = 4 edges), float4 loads, 3-shfl reduction.
// out[w] = dot(z[a], z[b]).  Tail duty: re-zero g_ideg for the next replay.
__global__ void decode_kernel(const int* __restrict__ pos,
                              const int* __restrict__ neg, long long E,
                              const float* __restrict__ Z, float* __restrict__ out,
                              int* __restrict__ ideg, int n) {
    long long tid = (long long)blockIdx.x * blockDim.x + threadIdx.x;
    if (tid < n) ideg[tid] = 0;     // reset degrees for next replay

    int lane = threadIdx.x & 31;
    int grp = lane >> 3;            // 0..3: edge within warp
    int j = lane & 7;               // float4 slot (row = 16 float4s, j and j+8)
    long long warp0 = tid >> 5;
    long long nwarps = ((long long)gridDim.x * blockDim.x) >> 5;
    long long twoE = 2 * E;
    const float4* Z4 = (const float4*)Z;

    for (long long w4 = warp0 * 4; w4 < twoE; w4 += nwarps * 4) {
        long long w = w4 + grp;
        bool valid = w < twoE;
        int a = 0, b = 0;
        if (valid) {
            if (w < E) { a = pos[w]; b = pos[E + w]; }
            else       { a = neg[w - E]; b = neg[w]; }   // neg[E + (w-E)] == neg[w]
        }
        long long ra = (long long)a * 16;
        long long rb = (long long)b * 16;
        float4 a0 = Z4[ra + j];
        float4 a1 = Z4[ra + 8 + j];
        float4 b0 = Z4[rb + j];
        float4 b1 = Z4[rb + 8 + j];
        float s = a0.x * b0.x + a0.y * b0.y + a0.z * b0.z + a0.w * b0.w
                + a1.x * b1.x + a1.y * b1.y + a1.z * b1.z + a1.w * b1.w;
        s += __shfl_xor_sync(0xffffffffu, s, 1);
        s += __shfl_xor_sync(0xffffffffu, s, 2);
        s += __shfl_xor_sync(0xffffffffu, s, 4);
        if (valid && j == 0) out[w] = s;
    }
}

extern "C" void kernel_launch(void* const* d_in, const int* in_sizes, int n_in,
                              void* d_out, int out_size) {
    const float* x   = (const float*)d_in[0];
    const void*  pos = d_in[1];
    const void*  neg = d_in[2];
    const float* W1  = (const float*)d_in[3];
    const float* b1  = (const float*)d_in[4];
    const float* W2  = (const float*)d_in[5];
    const float* b2  = (const float*)d_in[6];
    float* out = (float*)d_out;

    long long E = (long long)in_sizes[1] / 2;   // 1.6M
    int n = NN;
    int Fin = in_sizes[0] / n;                  // 256

    int *pos32, *neg32, *csr, *ideg, *offs, *cursor;
    float *dis, *h, *acc1, *t, *acc2;
    cudaGetSymbolAddress((void**)&pos32,  g_pos32);
    cudaGetSymbolAddress((void**)&neg32,  g_neg32);
    cudaGetSymbolAddress((void**)&csr,    g_csr);
    cudaGetSymbolAddress((void**)&ideg,   g_ideg);
    cudaGetSymbolAddress((void**)&offs,   g_offs);
    cudaGetSymbolAddress((void**)&cursor, g_cursor);
    cudaGetSymbolAddress((void**)&dis,    g_dis);
    cudaGetSymbolAddress((void**)&h,      g_h);
    cudaGetSymbolAddress((void**)&acc1,   g_acc1);
    cudaGetSymbolAddress((void**)&t,      g_t);
    cudaGetSymbolAddress((void**)&acc2,   g_acc2);

    detect_kernel<<<1, 64>>>((const unsigned int*)pos);

    convdeg_kernel<<<GS_BLOCKS, GS_THREADS>>>(pos, neg, pos32, neg32, ideg, 2 * E);
    scan_kernel<<<1, 1024>>>(ideg, offs, cursor, dis, n);
    fill_kernel<<<GS_BLOCKS, GS_THREADS>>>(pos32, E, cursor, csr);

    int gblocks = (n + 63) / 64;
    gemm_kernel<<<gblocks, 256>>>(x, W1, b1, dis, h, n, Fin);
    gather_kernel<<<GS_BLOCKS, GS_THREADS>>>(offs, csr, dis, h, acc1, n, 1);
    gemm_kernel<<<gblocks, 256>>>(acc1, W2, b2, dis, t, n, 64);
    gather_kernel<<<GS_BLOCKS, GS_THREADS>>>(offs, csr, dis, t, acc2, n, 0);

    decode_kernel<<<GS_BLOCKS, GS_THREADS>>>(pos32, neg32, E, acc2, out, ideg, n);
}

// round 5
// speedup vs baseline: 1.8330x; 1.4732x over previous
#include <cuda_runtime.h>
#include <cstdint>

#define NN 100000
#define EMAX 1600000
#define GS_BLOCKS 2368          // 16 CTAs/SM * 148 SMs
#define GS_THREADS 256

// -------- scratch (static device globals; no runtime allocation) --------
__device__ __align__(16) int   g_pos32[2 * EMAX];
__device__ __align__(16) int   g_neg32[2 * EMAX];
__device__ __align__(16) int   g_csr[EMAX];        // neighbor col ids grouped by row
__device__ __align__(16) int   g_ideg[NN];         // zero-initialized at load; decode re-zeros
__device__ __align__(16) int   g_offs[NN + 1];
__device__ __align__(16) int   g_cursor[NN];
__device__ __align__(16) float g_dis[NN];
__device__ __align__(16) float g_h[NN * 64];       // dis[i]*(x@W1+b1)
__device__ __align__(16) float g_acc1[NN * 64];    // relu(layer1 aggregated)
__device__ __align__(16) float g_t[NN * 64];       // dis[i]*(acc1@W2+b2)
__device__ __align__(16) float g_acc2[NN * 64];    // z
__device__ int g_is64;

// -------- dtype-agnostic index load (int32 vs int64, decided at runtime) ----
__device__ __forceinline__ long long ldidx(const void* p, long long i) {
    if (g_is64) return ((const long long*)p)[i];
    return (long long)((const int*)p)[i];
}

// Detect int64 vs int32 indices (odd 32-bit words all zero => int64, since ids < 2^17).
__global__ void detect_kernel(const unsigned int* p) {
    __shared__ int ok;
    if (threadIdx.x == 0) ok = 1;
    __syncthreads();
    if (p[2 * threadIdx.x + 1] != 0u) atomicExch(&ok, 0);
    __syncthreads();
    if (threadIdx.x == 0) g_is64 = ok;
}

// Convert both index arrays to int32 and count row degrees, one pass, grid-stride.
__global__ void convdeg_kernel(const void* __restrict__ pos,
                               const void* __restrict__ neg,
                               int* __restrict__ pos32, int* __restrict__ neg32,
                               int* __restrict__ ideg, long long twoE) {
    long long E = twoE >> 1;
    long long stride = (long long)gridDim.x * blockDim.x;
    for (long long i = (long long)blockIdx.x * blockDim.x + threadIdx.x;
         i < twoE; i += stride) {
        int pv = (int)ldidx(pos, i);
        pos32[i] = pv;
        neg32[i] = (int)ldidx(neg, i);
        if (i < E) atomicAdd(&ideg[pv], 1);
    }
}

// Single-block exclusive scan over n=100k degrees; writes offs[0..n], cursor, dis.
__global__ void scan_kernel(const int* __restrict__ ideg, int* offs, int* cursor,
                            float* dis, int n) {
    __shared__ int part[1024];
    int tid = threadIdx.x;
    int per = (n + 1023) / 1024;
    int start = tid * per;
    int end = min(start + per, n);
    int s = 0;
    for (int i = start; i < end; i++) s += ideg[i];
    part[tid] = s;
    __syncthreads();
    for (int off = 1; off < 1024; off <<= 1) {
        int t2 = (tid >= off) ? part[tid - off] : 0;
        __syncthreads();
        part[tid] += t2;
        __syncthreads();
    }
    int run = part[tid] - s;   // exclusive base
    for (int i = start; i < end; i++) {
        int d = ideg[i];
        offs[i] = run;
        cursor[i] = run;
        dis[i] = (d > 0) ? rsqrtf((float)d) : 0.0f;
        run += d;
    }
    if (tid == 0) offs[n] = part[1023];
}

__global__ void fill_kernel(const int* __restrict__ pos, long long E,
                            int* cursor, int* csr) {
    long long stride = (long long)gridDim.x * blockDim.x;
    for (long long e = (long long)blockIdx.x * blockDim.x + threadIdx.x;
         e < E; e += stride) {
        int row = pos[e];
        int col = pos[E + e];
        int slot = atomicAdd(&cursor[row], 1);
        csr[slot] = col;
    }
}

// GEMM v2: Y[row,:] = dis[row]*(X[row,:] @ W + b).
// 256 threads/block, 256-row x 64-col tile, thread = 4 rows x 16 cols (64 acc).
// X tile stored k-major in smem so 4 row-values per k = one LDS.128.
__global__ void __launch_bounds__(256, 2)
gemm_kernel(const float* __restrict__ X,
            const float* __restrict__ W,
            const float* __restrict__ bias,
            const float* __restrict__ dis,
            float* __restrict__ Y,
            int n, int K) {
    __shared__ float xs[16 * 256];   // [k][row] 16 KB
    __shared__ float Ws[16 * 64];    // [k][col] 4 KB

    int tid = threadIdx.x;
    int rg = tid >> 2;               // 0..63: row group (4 rows each)
    int cq = (tid & 3) * 16;         // col offset
    int row0 = blockIdx.x * 256;

    float acc[4][16];
#pragma unroll
    for (int r = 0; r < 4; r++)
#pragma unroll
        for (int c = 0; c < 16; c++) acc[r][c] = 0.0f;

    int myrow = row0 + tid;
    const float4* Xr = (const float4*)(X + (long long)myrow * K);
    bool rvalid = myrow < n;

    for (int kt = 0; kt < K; kt += 16) {
        // stage loads
        float4 wv = ((const float4*)(W + (long long)kt * 64))[tid];
        float4 v0 = make_float4(0.f, 0.f, 0.f, 0.f), v1 = v0, v2 = v0, v3 = v0;
        if (rvalid) {
            int kb = kt >> 2;
            v0 = __ldg(Xr + kb + 0);
            v1 = __ldg(Xr + kb + 1);
            v2 = __ldg(Xr + kb + 2);
            v3 = __ldg(Xr + kb + 3);
        }
        __syncthreads();
        ((float4*)Ws)[tid] = wv;
        xs[ 0 * 256 + tid] = v0.x; xs[ 1 * 256 + tid] = v0.y;
        xs[ 2 * 256 + tid] = v0.z; xs[ 3 * 256 + tid] = v0.w;
        xs[ 4 * 256 + tid] = v1.x; xs[ 5 * 256 + tid] = v1.y;
        xs[ 6 * 256 + tid] = v1.z; xs[ 7 * 256 + tid] = v1.w;
        xs[ 8 * 256 + tid] = v2.x; xs[ 9 * 256 + tid] = v2.y;
        xs[10 * 256 + tid] = v2.z; xs[11 * 256 + tid] = v2.w;
        xs[12 * 256 + tid] = v3.x; xs[13 * 256 + tid] = v3.y;
        xs[14 * 256 + tid] = v3.z; xs[15 * 256 + tid] = v3.w;
        __syncthreads();

#pragma unroll
        for (int k = 0; k < 16; k++) {
            float4 xv = *(const float4*)(xs + k * 256 + rg * 4);
            const float4* wr = (const float4*)(Ws + k * 64 + cq);
            float4 w0 = wr[0], w1 = wr[1], w2 = wr[2], w3 = wr[3];
            float wf[16] = {w0.x, w0.y, w0.z, w0.w, w1.x, w1.y, w1.z, w1.w,
                            w2.x, w2.y, w2.z, w2.w, w3.x, w3.y, w3.z, w3.w};
            float xf[4] = {xv.x, xv.y, xv.z, xv.w};
#pragma unroll
            for (int r = 0; r < 4; r++)
#pragma unroll
                for (int c = 0; c < 16; c++)
                    acc[r][c] += xf[r] * wf[c];
        }
    }

#pragma unroll
    for (int r = 0; r < 4; r++) {
        int row = row0 + rg * 4 + r;
        if (row < n) {
            float dr = dis[row];
            float* yp = Y + (long long)row * 64 + cq;
#pragma unroll
            for (int q = 0; q < 4; q++) {
                float4 o;
                o.x = (acc[r][q * 4 + 0] + bias[cq + q * 4 + 0]) * dr;
                o.y = (acc[r][q * 4 + 1] + bias[cq + q * 4 + 1]) * dr;
                o.z = (acc[r][q * 4 + 2] + bias[cq + q * 4 + 2]) * dr;
                o.w = (acc[r][q * 4 + 3] + bias[cq + q * 4 + 3]) * dr;
                *(float4*)(yp + q * 4) = o;
            }
        }
    }
}

// Gather: warp per node, half-warp per neighbor, float4 lanes, 8 neighbors/iter.
// out[row,:] = act( dis[row] * sum_{col in CSR[row]} H[col,:] )
__global__ void gather_kernel(const int* __restrict__ offs,
                              const int* __restrict__ csr,
                              const float* __restrict__ dis,
                              const float* __restrict__ H,
                              float* __restrict__ out,
                              int n, int do_relu) {
    int lane = threadIdx.x & 31;
    int half = lane >> 4;        // 0 or 1
    int j = lane & 15;           // float4 slot within the 64-float row
    long long warp0 = ((long long)blockIdx.x * blockDim.x + threadIdx.x) >> 5;
    long long nwarps = ((long long)gridDim.x * blockDim.x) >> 5;
    const float4* H4 = (const float4*)H;

    for (long long node = warp0; node < n; node += nwarps) {
        int s = offs[node];
        int e = offs[node + 1];
        float4 acc = make_float4(0.f, 0.f, 0.f, 0.f);

        int base = s;
        // main loop: 8 neighbors per iteration (4 per half-warp), MLP=4/lane
        for (; base + 8 <= e; base += 8) {
            int c0 = csr[base + 0 + half];
            int c1 = csr[base + 2 + half];
            int c2 = csr[base + 4 + half];
            int c3 = csr[base + 6 + half];
            float4 v0 = H4[(long long)c0 * 16 + j];
            float4 v1 = H4[(long long)c1 * 16 + j];
            float4 v2 = H4[(long long)c2 * 16 + j];
            float4 v3 = H4[(long long)c3 * 16 + j];
            acc.x += (v0.x + v1.x) + (v2.x + v3.x);
            acc.y += (v0.y + v1.y) + (v2.y + v3.y);
            acc.z += (v0.z + v1.z) + (v2.z + v3.z);
            acc.w += (v0.w + v1.w) + (v2.w + v3.w);
        }
        // tail
        for (; base < e; base += 2) {
            int my = base + half;
            if (my < e) {
                int c = csr[my];
                float4 v = H4[(long long)c * 16 + j];
                acc.x += v.x; acc.y += v.y; acc.z += v.z; acc.w += v.w;
            }
        }

        acc.x += __shfl_xor_sync(0xffffffffu, acc.x, 16);
        acc.y += __shfl_xor_sync(0xffffffffu, acc.y, 16);
        acc.z += __shfl_xor_sync(0xffffffffu, acc.z, 16);
        acc.w += __shfl_xor_sync(0xffffffffu, acc.w, 16);

        if (half == 0) {
            float dr = dis[node];
            acc.x *= dr; acc.y *= dr; acc.z *= dr; acc.w *= dr;
            if (do_relu) {
                acc.x = fmaxf(acc.x, 0.f);
                acc.y = fmaxf(acc.y, 0.f);
                acc.z = fmaxf(acc.z, 0.f);
                acc.w = fmaxf(acc.w, 0.f);
            }
            ((float4*)out)[node * 16 + j] = acc;
        }
    }
}

// Decode: 8 lanes per edge (warp = 4 edges), float4 loads, 3-shfl reduction.
// Tail duty: re-zero g_ideg for the next replay.
__global__ void decode_kernel(const int* __restrict__ pos,
                              const int* __restrict__ neg, long long E,
                              const float* __restrict__ Z, float* __restrict__ out,
                              int* __restrict__ ideg, int n) {
    long long tid = (long long)blockIdx.x * blockDim.x + threadIdx.x;
    if (tid < n) ideg[tid] = 0;     // reset degrees for next replay

    int lane = threadIdx.x & 31;
    int grp = lane >> 3;            // 0..3: edge within warp
    int j = lane & 7;               // float4 slot (row = 16 float4s, j and j+8)
    long long warp0 = tid >> 5;
    long long nwarps = ((long long)gridDim.x * blockDim.x) >> 5;
    long long twoE = 2 * E;
    const float4* Z4 = (const float4*)Z;

    for (long long w4 = warp0 * 4; w4 < twoE; w4 += nwarps * 4) {
        long long w = w4 + grp;
        bool valid = w < twoE;
        int a = 0, b = 0;
        if (valid) {
            if (w < E) { a = pos[w]; b = pos[E + w]; }
            else       { a = neg[w - E]; b = neg[w]; }   // neg[E + (w-E)] == neg[w]
        }
        long long ra = (long long)a * 16;
        long long rb = (long long)b * 16;
        float4 a0 = Z4[ra + j];
        float4 a1 = Z4[ra + 8 + j];
        float4 b0 = Z4[rb + j];
        float4 b1 = Z4[rb + 8 + j];
        float s = a0.x * b0.x + a0.y * b0.y + a0.z * b0.z + a0.w * b0.w
                + a1.x * b1.x + a1.y * b1.y + a1.z * b1.z + a1.w * b1.w;
        s += __shfl_xor_sync(0xffffffffu, s, 1);
        s += __shfl_xor_sync(0xffffffffu, s, 2);
        s += __shfl_xor_sync(0xffffffffu, s, 4);
        if (valid && j == 0) out[w] = s;
    }
}

extern "C" void kernel_launch(void* const* d_in, const int* in_sizes, int n_in,
                              void* d_out, int out_size) {
    const float* x   = (const float*)d_in[0];
    const void*  pos = d_in[1];
    const void*  neg = d_in[2];
    const float* W1  = (const float*)d_in[3];
    const float* b1  = (const float*)d_in[4];
    const float* W2  = (const float*)d_in[5];
    const float* b2  = (const float*)d_in[6];
    float* out = (float*)d_out;

    long long E = (long long)in_sizes[1] / 2;   // 1.6M
    int n = NN;
    int Fin = in_sizes[0] / n;                  // 256

    int *pos32, *neg32, *csr, *ideg, *offs, *cursor;
    float *dis, *h, *acc1, *t, *acc2;
    cudaGetSymbolAddress((void**)&pos32,  g_pos32);
    cudaGetSymbolAddress((void**)&neg32,  g_neg32);
    cudaGetSymbolAddress((void**)&csr,    g_csr);
    cudaGetSymbolAddress((void**)&ideg,   g_ideg);
    cudaGetSymbolAddress((void**)&offs,   g_offs);
    cudaGetSymbolAddress((void**)&cursor, g_cursor);
    cudaGetSymbolAddress((void**)&dis,    g_dis);
    cudaGetSymbolAddress((void**)&h,      g_h);
    cudaGetSymbolAddress((void**)&acc1,   g_acc1);
    cudaGetSymbolAddress((void**)&t,      g_t);
    cudaGetSymbolAddress((void**)&acc2,   g_acc2);

    detect_kernel<<<1, 64>>>((const unsigned int*)pos);

    convdeg_kernel<<<GS_BLOCKS, GS_THREADS>>>(pos, neg, pos32, neg32, ideg, 2 * E);
    scan_kernel<<<1, 1024>>>(ideg, offs, cursor, dis, n);
    fill_kernel<<<GS_BLOCKS, GS_THREADS>>>(pos32, E, cursor, csr);

    int gblocks = (n + 255) / 256;
    gemm_kernel<<<gblocks, 256>>>(x, W1, b1, dis, h, n, Fin);
    gather_kernel<<<GS_BLOCKS, GS_THREADS>>>(offs, csr, dis, h, acc1, n, 1);
    gemm_kernel<<<gblocks, 256>>>(acc1, W2, b2, dis, t, n, 64);
    gather_kernel<<<GS_BLOCKS, GS_THREADS>>>(offs, csr, dis, t, acc2, n, 0);

    decode_kernel<<<GS_BLOCKS, GS_THREADS>>>(pos32, neg32, E, acc2, out, ideg, n);
}

// round 6
// speedup vs baseline: 1.9369x; 1.0567x over previous
#include <cuda_runtime.h>
#include <cuda_fp16.h>
#include <cstdint>

#define NN 100000
#define EMAX 1600000
#define GS_BLOCKS 2368          // 16 CTAs/SM * 148 SMs
#define GS_THREADS 256

// -------- scratch (static device globals; no runtime allocation) --------
__device__ __align__(16) int    g_pos32[2 * EMAX];
__device__ __align__(16) int    g_neg32[2 * EMAX];
__device__ __align__(16) int    g_csr[EMAX];       // neighbor col ids grouped by row
__device__ __align__(16) int    g_ideg[NN];        // zero-initialized at load; decode re-zeros
__device__ __align__(16) int    g_offs[NN + 1];
__device__ __align__(16) int    g_cursor[NN];
__device__ __align__(16) float  g_dis[NN];
__device__ __align__(16) float  g_h[NN * 64];      // dis[i]*(x@W1+b1)
__device__ __align__(16) float  g_acc1[NN * 64];   // relu(layer1 aggregated)
__device__ __align__(16) float  g_t[NN * 64];      // dis[i]*(acc1@W2+b2)
__device__ __align__(16) __half g_z[NN * 64];      // z in fp16 (decode-only consumer)
__device__ int g_is64;

// -------- dtype-agnostic index load (int32 vs int64, decided at runtime) ----
__device__ __forceinline__ long long ldidx(const void* p, long long i) {
    if (g_is64) return ((const long long*)p)[i];
    return (long long)((const int*)p)[i];
}

// Detect int64 vs int32 indices (odd 32-bit words all zero => int64, since ids < 2^17).
__global__ void detect_kernel(const unsigned int* p) {
    __shared__ int ok;
    if (threadIdx.x == 0) ok = 1;
    __syncthreads();
    if (p[2 * threadIdx.x + 1] != 0u) atomicExch(&ok, 0);
    __syncthreads();
    if (threadIdx.x == 0) g_is64 = ok;
}

// Convert both index arrays to int32 and count row degrees, one pass, grid-stride.
__global__ void convdeg_kernel(const void* __restrict__ pos,
                               const void* __restrict__ neg,
                               int* __restrict__ pos32, int* __restrict__ neg32,
                               int* __restrict__ ideg, long long twoE) {
    long long E = twoE >> 1;
    long long stride = (long long)gridDim.x * blockDim.x;
    for (long long i = (long long)blockIdx.x * blockDim.x + threadIdx.x;
         i < twoE; i += stride) {
        int pv = (int)ldidx(pos, i);
        pos32[i] = pv;
        neg32[i] = (int)ldidx(neg, i);
        if (i < E) atomicAdd(&ideg[pv], 1);
    }
}

// Single-block exclusive scan over n=100k degrees; writes offs[0..n], cursor, dis.
__global__ void scan_kernel(const int* __restrict__ ideg, int* offs, int* cursor,
                            float* dis, int n) {
    __shared__ int part[1024];
    int tid = threadIdx.x;
    int per = (n + 1023) / 1024;
    int start = tid * per;
    int end = min(start + per, n);
    int s = 0;
    for (int i = start; i < end; i++) s += ideg[i];
    part[tid] = s;
    __syncthreads();
    for (int off = 1; off < 1024; off <<= 1) {
        int t2 = (tid >= off) ? part[tid - off] : 0;
        __syncthreads();
        part[tid] += t2;
        __syncthreads();
    }
    int run = part[tid] - s;   // exclusive base
    for (int i = start; i < end; i++) {
        int d = ideg[i];
        offs[i] = run;
        cursor[i] = run;
        dis[i] = (d > 0) ? rsqrtf((float)d) : 0.0f;
        run += d;
    }
    if (tid == 0) offs[n] = part[1023];
}

__global__ void fill_kernel(const int* __restrict__ pos, long long E,
                            int* cursor, int* csr) {
    long long stride = (long long)gridDim.x * blockDim.x;
    for (long long e = (long long)blockIdx.x * blockDim.x + threadIdx.x;
         e < E; e += stride) {
        int row = pos[e];
        int col = pos[E + e];
        int slot = atomicAdd(&cursor[row], 1);
        csr[slot] = col;
    }
}

// GEMM: Y[row,:] = dis[row]*(X[row,:] @ W + b).
// 256 threads/block, 256-row x 64-col tile, thread = 4 rows x 16 cols (64 acc).
__global__ void __launch_bounds__(256, 2)
gemm_kernel(const float* __restrict__ X,
            const float* __restrict__ W,
            const float* __restrict__ bias,
            const float* __restrict__ dis,
            float* __restrict__ Y,
            int n, int K) {
    __shared__ float xs[16 * 256];   // [k][row] 16 KB
    __shared__ float Ws[16 * 64];    // [k][col] 4 KB

    int tid = threadIdx.x;
    int rg = tid >> 2;               // 0..63: row group (4 rows each)
    int cq = (tid & 3) * 16;         // col offset
    int row0 = blockIdx.x * 256;

    float acc[4][16];
#pragma unroll
    for (int r = 0; r < 4; r++)
#pragma unroll
        for (int c = 0; c < 16; c++) acc[r][c] = 0.0f;

    int myrow = row0 + tid;
    const float4* Xr = (const float4*)(X + (long long)myrow * K);
    bool rvalid = myrow < n;

    for (int kt = 0; kt < K; kt += 16) {
        float4 wv = ((const float4*)(W + (long long)kt * 64))[tid];
        float4 v0 = make_float4(0.f, 0.f, 0.f, 0.f), v1 = v0, v2 = v0, v3 = v0;
        if (rvalid) {
            int kb = kt >> 2;
            v0 = __ldg(Xr + kb + 0);
            v1 = __ldg(Xr + kb + 1);
            v2 = __ldg(Xr + kb + 2);
            v3 = __ldg(Xr + kb + 3);
        }
        __syncthreads();
        ((float4*)Ws)[tid] = wv;
        xs[ 0 * 256 + tid] = v0.x; xs[ 1 * 256 + tid] = v0.y;
        xs[ 2 * 256 + tid] = v0.z; xs[ 3 * 256 + tid] = v0.w;
        xs[ 4 * 256 + tid] = v1.x; xs[ 5 * 256 + tid] = v1.y;
        xs[ 6 * 256 + tid] = v1.z; xs[ 7 * 256 + tid] = v1.w;
        xs[ 8 * 256 + tid] = v2.x; xs[ 9 * 256 + tid] = v2.y;
        xs[10 * 256 + tid] = v2.z; xs[11 * 256 + tid] = v2.w;
        xs[12 * 256 + tid] = v3.x; xs[13 * 256 + tid] = v3.y;
        xs[14 * 256 + tid] = v3.z; xs[15 * 256 + tid] = v3.w;
        __syncthreads();

#pragma unroll
        for (int k = 0; k < 16; k++) {
            float4 xv = *(const float4*)(xs + k * 256 + rg * 4);
            const float4* wr = (const float4*)(Ws + k * 64 + cq);
            float4 w0 = wr[0], w1 = wr[1], w2 = wr[2], w3 = wr[3];
            float wf[16] = {w0.x, w0.y, w0.z, w0.w, w1.x, w1.y, w1.z, w1.w,
                            w2.x, w2.y, w2.z, w2.w, w3.x, w3.y, w3.z, w3.w};
            float xf[4] = {xv.x, xv.y, xv.z, xv.w};
#pragma unroll
            for (int r = 0; r < 4; r++)
#pragma unroll
                for (int c = 0; c < 16; c++)
                    acc[r][c] += xf[r] * wf[c];
        }
    }

#pragma unroll
    for (int r = 0; r < 4; r++) {
        int row = row0 + rg * 4 + r;
        if (row < n) {
            float dr = dis[row];
            float* yp = Y + (long long)row * 64 + cq;
#pragma unroll
            for (int q = 0; q < 4; q++) {
                float4 o;
                o.x = (acc[r][q * 4 + 0] + bias[cq + q * 4 + 0]) * dr;
                o.y = (acc[r][q * 4 + 1] + bias[cq + q * 4 + 1]) * dr;
                o.z = (acc[r][q * 4 + 2] + bias[cq + q * 4 + 2]) * dr;
                o.w = (acc[r][q * 4 + 3] + bias[cq + q * 4 + 3]) * dr;
                *(float4*)(yp + q * 4) = o;
            }
        }
    }
}

// Gather: warp per node, half-warp per neighbor, float4 lanes, 8 neighbors/iter.
// agg = dis[row] * sum_{col} H[col,:]. Epilogue: relu->float out (layer 1) or
// fp16 z out (layer 2, consumed only by decode).
__global__ void gather_kernel(const int* __restrict__ offs,
                              const int* __restrict__ csr,
                              const float* __restrict__ dis,
                              const float* __restrict__ H,
                              float* __restrict__ outf,      // layer-1 output (or null)
                              __half* __restrict__ outh,     // layer-2 fp16 z (or null)
                              int n) {
    int lane = threadIdx.x & 31;
    int half_id = lane >> 4;     // 0 or 1
    int j = lane & 15;           // float4 slot within the 64-float row
    long long warp0 = ((long long)blockIdx.x * blockDim.x + threadIdx.x) >> 5;
    long long nwarps = ((long long)gridDim.x * blockDim.x) >> 5;
    const float4* H4 = (const float4*)H;

    for (long long node = warp0; node < n; node += nwarps) {
        int s = offs[node];
        int e = offs[node + 1];
        float4 acc = make_float4(0.f, 0.f, 0.f, 0.f);

        int base = s;
        for (; base + 8 <= e; base += 8) {
            int c0 = csr[base + 0 + half_id];
            int c1 = csr[base + 2 + half_id];
            int c2 = csr[base + 4 + half_id];
            int c3 = csr[base + 6 + half_id];
            float4 v0 = H4[(long long)c0 * 16 + j];
            float4 v1 = H4[(long long)c1 * 16 + j];
            float4 v2 = H4[(long long)c2 * 16 + j];
            float4 v3 = H4[(long long)c3 * 16 + j];
            acc.x += (v0.x + v1.x) + (v2.x + v3.x);
            acc.y += (v0.y + v1.y) + (v2.y + v3.y);
            acc.z += (v0.z + v1.z) + (v2.z + v3.z);
            acc.w += (v0.w + v1.w) + (v2.w + v3.w);
        }
        for (; base < e; base += 2) {
            int my = base + half_id;
            if (my < e) {
                int c = csr[my];
                float4 v = H4[(long long)c * 16 + j];
                acc.x += v.x; acc.y += v.y; acc.z += v.z; acc.w += v.w;
            }
        }

        acc.x += __shfl_xor_sync(0xffffffffu, acc.x, 16);
        acc.y += __shfl_xor_sync(0xffffffffu, acc.y, 16);
        acc.z += __shfl_xor_sync(0xffffffffu, acc.z, 16);
        acc.w += __shfl_xor_sync(0xffffffffu, acc.w, 16);

        if (half_id == 0) {
            float dr = dis[node];
            acc.x *= dr; acc.y *= dr; acc.z *= dr; acc.w *= dr;
            if (outf) {
                acc.x = fmaxf(acc.x, 0.f);
                acc.y = fmaxf(acc.y, 0.f);
                acc.z = fmaxf(acc.z, 0.f);
                acc.w = fmaxf(acc.w, 0.f);
                ((float4*)outf)[node * 16 + j] = acc;
            } else {
                __half2 p0 = __floats2half2_rn(acc.x, acc.y);
                __half2 p1 = __floats2half2_rn(acc.z, acc.w);
                uint2 pk;
                pk.x = *(unsigned int*)&p0;
                pk.y = *(unsigned int*)&p1;
                ((uint2*)outh)[node * 16 + j] = pk;
            }
        }
    }
}

// Decode: 8 lanes/edge (warp = 4 edges). fp16 z rows: 128B, one LDG.128 per
// endpoint per lane. fp32 accumulate, 3-shfl reduce.
// Tail duty: re-zero g_ideg for the next replay.
__global__ void decode_kernel(const int* __restrict__ pos,
                              const int* __restrict__ neg, long long E,
                              const __half* __restrict__ Zh, float* __restrict__ out,
                              int* __restrict__ ideg, int n) {
    long long tid = (long long)blockIdx.x * blockDim.x + threadIdx.x;
    if (tid < n) ideg[tid] = 0;     // reset degrees for next replay

    int lane = threadIdx.x & 31;
    int grp = lane >> 3;            // 0..3: edge within warp
    int j = lane & 7;               // uint4 slot (row = 8 uint4 = 64 halves)
    long long warp0 = tid >> 5;
    long long nwarps = ((long long)gridDim.x * blockDim.x) >> 5;
    long long twoE = 2 * E;
    const uint4* Z8 = (const uint4*)Zh;   // 8 halves per uint4

    for (long long w4 = warp0 * 4; w4 < twoE; w4 += nwarps * 4) {
        long long w = w4 + grp;
        bool valid = w < twoE;
        int a = 0, b = 0;
        if (valid) {
            if (w < E) { a = pos[w]; b = pos[E + w]; }
            else       { a = neg[w - E]; b = neg[w]; }   // neg[E + (w-E)] == neg[w]
        }
        uint4 ua = Z8[(long long)a * 8 + j];
        uint4 ub = Z8[(long long)b * 8 + j];
        const __half2* pa = (const __half2*)&ua;
        const __half2* pb = (const __half2*)&ub;
        float s = 0.f;
#pragma unroll
        for (int t = 0; t < 4; t++) {
            float2 fa = __half22float2(pa[t]);
            float2 fb = __half22float2(pb[t]);
            s += fa.x * fb.x + fa.y * fb.y;
        }
        s += __shfl_xor_sync(0xffffffffu, s, 1);
        s += __shfl_xor_sync(0xffffffffu, s, 2);
        s += __shfl_xor_sync(0xffffffffu, s, 4);
        if (valid && j == 0) out[w] = s;
    }
}

extern "C" void kernel_launch(void* const* d_in, const int* in_sizes, int n_in,
                              void* d_out, int out_size) {
    const float* x   = (const float*)d_in[0];
    const void*  pos = d_in[1];
    const void*  neg = d_in[2];
    const float* W1  = (const float*)d_in[3];
    const float* b1  = (const float*)d_in[4];
    const float* W2  = (const float*)d_in[5];
    const float* b2  = (const float*)d_in[6];
    float* out = (float*)d_out;

    long long E = (long long)in_sizes[1] / 2;   // 1.6M
    int n = NN;
    int Fin = in_sizes[0] / n;                  // 256

    int *pos32, *neg32, *csr, *ideg, *offs, *cursor;
    float *dis, *h, *acc1, *t;
    __half* z;
    cudaGetSymbolAddress((void**)&pos32,  g_pos32);
    cudaGetSymbolAddress((void**)&neg32,  g_neg32);
    cudaGetSymbolAddress((void**)&csr,    g_csr);
    cudaGetSymbolAddress((void**)&ideg,   g_ideg);
    cudaGetSymbolAddress((void**)&offs,   g_offs);
    cudaGetSymbolAddress((void**)&cursor, g_cursor);
    cudaGetSymbolAddress((void**)&dis,    g_dis);
    cudaGetSymbolAddress((void**)&h,      g_h);
    cudaGetSymbolAddress((void**)&acc1,   g_acc1);
    cudaGetSymbolAddress((void**)&t,      g_t);
    cudaGetSymbolAddress((void**)&z,      g_z);

    detect_kernel<<<1, 64>>>((const unsigned int*)pos);

    convdeg_kernel<<<GS_BLOCKS, GS_THREADS>>>(pos, neg, pos32, neg32, ideg, 2 * E);
    scan_kernel<<<1, 1024>>>(ideg, offs, cursor, dis, n);
    fill_kernel<<<GS_BLOCKS, GS_THREADS>>>(pos32, E, cursor, csr);

    int gblocks = (n + 255) / 256;
    gemm_kernel<<<gblocks, 256>>>(x, W1, b1, dis, h, n, Fin);
    gather_kernel<<<GS_BLOCKS, GS_THREADS>>>(offs, csr, dis, h, acc1, (__half*)0, n);
    gemm_kernel<<<gblocks, 256>>>(acc1, W2, b2, dis, t, n, 64);
    gather_kernel<<<GS_BLOCKS, GS_THREADS>>>(offs, csr, dis, t, (float*)0, z, n);

    decode_kernel<<<GS_BLOCKS, GS_THREADS>>>(pos32, neg32, E, z, out, ideg, n);
}

// round 7
// speedup vs baseline: 2.0182x; 1.0420x over previous
#include <cuda_runtime.h>
#include <cuda_fp16.h>
#include <cstdint>

#define NN 100000
#define EMAX 1600000
#define GS_BLOCKS 2368          // 16 CTAs/SM * 148 SMs
#define GS_THREADS 256

// -------- scratch (static device globals; no runtime allocation) --------
__device__ __align__(16) int    g_pos32[2 * EMAX];
__device__ __align__(16) int    g_neg32[2 * EMAX];
__device__ __align__(16) int    g_csr[EMAX];       // neighbor col ids grouped by row
__device__ __align__(16) int    g_ideg[NN];        // zero-initialized at load; decode re-zeros
__device__ __align__(16) int    g_offs[NN + 1];
__device__ __align__(16) int    g_cursor[NN];
__device__ __align__(16) float  g_dis[NN];
__device__ __align__(16) __half g_h[NN * 64];      // fp16: dis[i]*(x@W1+b1)
__device__ __align__(16) float  g_acc1[NN * 64];   // fp32: relu(layer1 aggregated)
__device__ __align__(16) __half g_t[NN * 64];      // fp16: dis[i]*(acc1@W2+b2)
__device__ __align__(16) __half g_z[NN * 64];      // fp16 z (decode-only consumer)
__device__ int g_is64;

// -------- dtype-agnostic index load (int32 vs int64, decided at runtime) ----
__device__ __forceinline__ long long ldidx(const void* p, long long i) {
    if (g_is64) return ((const long long*)p)[i];
    return (long long)((const int*)p)[i];
}

// Detect int64 vs int32 indices (odd 32-bit words all zero => int64, since ids < 2^17).
__global__ void detect_kernel(const unsigned int* p) {
    __shared__ int ok;
    if (threadIdx.x == 0) ok = 1;
    __syncthreads();
    if (p[2 * threadIdx.x + 1] != 0u) atomicExch(&ok, 0);
    __syncthreads();
    if (threadIdx.x == 0) g_is64 = ok;
}

// Convert both index arrays to int32 and count row degrees, one pass, grid-stride.
__global__ void convdeg_kernel(const void* __restrict__ pos,
                               const void* __restrict__ neg,
                               int* __restrict__ pos32, int* __restrict__ neg32,
                               int* __restrict__ ideg, long long twoE) {
    long long E = twoE >> 1;
    long long stride = (long long)gridDim.x * blockDim.x;
    for (long long i = (long long)blockIdx.x * blockDim.x + threadIdx.x;
         i < twoE; i += stride) {
        int pv = (int)ldidx(pos, i);
        pos32[i] = pv;
        neg32[i] = (int)ldidx(neg, i);
        if (i < E) atomicAdd(&ideg[pv], 1);
    }
}

// Single-block exclusive scan over n=100k degrees; writes offs[0..n], cursor, dis.
__global__ void scan_kernel(const int* __restrict__ ideg, int* offs, int* cursor,
                            float* dis, int n) {
    __shared__ int part[1024];
    int tid = threadIdx.x;
    int per = (n + 1023) / 1024;
    int start = tid * per;
    int end = min(start + per, n);
    int s = 0;
    for (int i = start; i < end; i++) s += ideg[i];
    part[tid] = s;
    __syncthreads();
    for (int off = 1; off < 1024; off <<= 1) {
        int t2 = (tid >= off) ? part[tid - off] : 0;
        __syncthreads();
        part[tid] += t2;
        __syncthreads();
    }
    int run = part[tid] - s;   // exclusive base
    for (int i = start; i < end; i++) {
        int d = ideg[i];
        offs[i] = run;
        cursor[i] = run;
        dis[i] = (d > 0) ? rsqrtf((float)d) : 0.0f;
        run += d;
    }
    if (tid == 0) offs[n] = part[1023];
}

__global__ void fill_kernel(const int* __restrict__ pos, long long E,
                            int* cursor, int* csr) {
    long long stride = (long long)gridDim.x * blockDim.x;
    for (long long e = (long long)blockIdx.x * blockDim.x + threadIdx.x;
         e < E; e += stride) {
        int row = pos[e];
        int col = pos[E + e];
        int slot = atomicAdd(&cursor[row], 1);
        csr[slot] = col;
    }
}

// GEMM: Yh[row,:] = fp16( dis[row]*(X[row,:] @ W + b) ).
// 256 threads/block, 256-row x 64-col tile, thread = 4 rows x 16 cols (64 acc).
__global__ void __launch_bounds__(256, 2)
gemm_kernel(const float* __restrict__ X,
            const float* __restrict__ W,
            const float* __restrict__ bias,
            const float* __restrict__ dis,
            __half* __restrict__ Yh,
            int n, int K) {
    __shared__ float xs[16 * 256];   // [k][row] 16 KB
    __shared__ float Ws[16 * 64];    // [k][col] 4 KB

    int tid = threadIdx.x;
    int rg = tid >> 2;               // 0..63: row group (4 rows each)
    int cq = (tid & 3) * 16;         // col offset
    int row0 = blockIdx.x * 256;

    float acc[4][16];
#pragma unroll
    for (int r = 0; r < 4; r++)
#pragma unroll
        for (int c = 0; c < 16; c++) acc[r][c] = 0.0f;

    int myrow = row0 + tid;
    const float4* Xr = (const float4*)(X + (long long)myrow * K);
    bool rvalid = myrow < n;

    for (int kt = 0; kt < K; kt += 16) {
        float4 wv = ((const float4*)(W + (long long)kt * 64))[tid];
        float4 v0 = make_float4(0.f, 0.f, 0.f, 0.f), v1 = v0, v2 = v0, v3 = v0;
        if (rvalid) {
            int kb = kt >> 2;
            v0 = __ldg(Xr + kb + 0);
            v1 = __ldg(Xr + kb + 1);
            v2 = __ldg(Xr + kb + 2);
            v3 = __ldg(Xr + kb + 3);
        }
        __syncthreads();
        ((float4*)Ws)[tid] = wv;
        xs[ 0 * 256 + tid] = v0.x; xs[ 1 * 256 + tid] = v0.y;
        xs[ 2 * 256 + tid] = v0.z; xs[ 3 * 256 + tid] = v0.w;
        xs[ 4 * 256 + tid] = v1.x; xs[ 5 * 256 + tid] = v1.y;
        xs[ 6 * 256 + tid] = v1.z; xs[ 7 * 256 + tid] = v1.w;
        xs[ 8 * 256 + tid] = v2.x; xs[ 9 * 256 + tid] = v2.y;
        xs[10 * 256 + tid] = v2.z; xs[11 * 256 + tid] = v2.w;
        xs[12 * 256 + tid] = v3.x; xs[13 * 256 + tid] = v3.y;
        xs[14 * 256 + tid] = v3.z; xs[15 * 256 + tid] = v3.w;
        __syncthreads();

#pragma unroll
        for (int k = 0; k < 16; k++) {
            float4 xv = *(const float4*)(xs + k * 256 + rg * 4);
            const float4* wr = (const float4*)(Ws + k * 64 + cq);
            float4 w0 = wr[0], w1 = wr[1], w2 = wr[2], w3 = wr[3];
            float wf[16] = {w0.x, w0.y, w0.z, w0.w, w1.x, w1.y, w1.z, w1.w,
                            w2.x, w2.y, w2.z, w2.w, w3.x, w3.y, w3.z, w3.w};
            float xf[4] = {xv.x, xv.y, xv.z, xv.w};
#pragma unroll
            for (int r = 0; r < 4; r++)
#pragma unroll
                for (int c = 0; c < 16; c++)
                    acc[r][c] += xf[r] * wf[c];
        }
    }

#pragma unroll
    for (int r = 0; r < 4; r++) {
        int row = row0 + rg * 4 + r;
        if (row < n) {
            float dr = dis[row];
            float o[16];
#pragma unroll
            for (int c = 0; c < 16; c++)
                o[c] = (acc[r][c] + bias[cq + c]) * dr;
            __half2 hh[8];
#pragma unroll
            for (int t = 0; t < 8; t++)
                hh[t] = __floats2half2_rn(o[2 * t], o[2 * t + 1]);
            uint4 pk0, pk1;
            pk0.x = *(unsigned int*)&hh[0]; pk0.y = *(unsigned int*)&hh[1];
            pk0.z = *(unsigned int*)&hh[2]; pk0.w = *(unsigned int*)&hh[3];
            pk1.x = *(unsigned int*)&hh[4]; pk1.y = *(unsigned int*)&hh[5];
            pk1.z = *(unsigned int*)&hh[6]; pk1.w = *(unsigned int*)&hh[7];
            __half* yp = Yh + (long long)row * 64 + cq;
            *(uint4*)yp = pk0;
            *(uint4*)(yp + 8) = pk1;
        }
    }
}

__device__ __forceinline__ void addu4(float acc[8], uint4 u) {
    const __half2* p = (const __half2*)&u;
#pragma unroll
    for (int t = 0; t < 4; t++) {
        float2 f = __half22float2(p[t]);
        acc[2 * t] += f.x;
        acc[2 * t + 1] += f.y;
    }
}

// Gather v3: warp per node, quarter-warp (8 lanes) per neighbor, fp16 rows
// (128B = 8 uint4), 16 neighbors/iter => MLP 4 per lane. fp32 accumulate.
// agg = dis[row] * sum_{col} H[col,:]; epilogue relu->fp32 (layer1) or fp16 z (layer2).
__global__ void gather_kernel(const int* __restrict__ offs,
                              const int* __restrict__ csr,
                              const float* __restrict__ dis,
                              const __half* __restrict__ H,
                              float* __restrict__ outf,      // layer-1 output (or null)
                              __half* __restrict__ outh,     // layer-2 fp16 z (or null)
                              int n) {
    int lane = threadIdx.x & 31;
    int q = lane >> 3;           // quarter 0..3
    int j = lane & 7;            // uint4 slot within the 64-half row
    long long warp0 = ((long long)blockIdx.x * blockDim.x + threadIdx.x) >> 5;
    long long nwarps = ((long long)gridDim.x * blockDim.x) >> 5;
    const uint4* H8 = (const uint4*)H;

    for (long long node = warp0; node < n; node += nwarps) {
        int s = offs[node];
        int e = offs[node + 1];
        float acc[8];
#pragma unroll
        for (int i = 0; i < 8; i++) acc[i] = 0.0f;

        int base = s;
        // 16 neighbors per iteration: 4 per quarter, MLP 4 per lane
        for (; base + 16 <= e; base += 16) {
            int c0 = csr[base + 0 + q];
            int c1 = csr[base + 4 + q];
            int c2 = csr[base + 8 + q];
            int c3 = csr[base + 12 + q];
            uint4 u0 = H8[(long long)c0 * 8 + j];
            uint4 u1 = H8[(long long)c1 * 8 + j];
            uint4 u2 = H8[(long long)c2 * 8 + j];
            uint4 u3 = H8[(long long)c3 * 8 + j];
            addu4(acc, u0);
            addu4(acc, u1);
            addu4(acc, u2);
            addu4(acc, u3);
        }
        // tail: 4 per iteration (1 per quarter)
        for (; base < e; base += 4) {
            int my = base + q;
            if (my < e) {
                uint4 u = H8[(long long)csr[my] * 8 + j];
                addu4(acc, u);
            }
        }

        // combine the 4 quarters
#pragma unroll
        for (int i = 0; i < 8; i++) {
            acc[i] += __shfl_xor_sync(0xffffffffu, acc[i], 8);
            acc[i] += __shfl_xor_sync(0xffffffffu, acc[i], 16);
        }

        if (q == 0) {
            float dr = dis[node];
#pragma unroll
            for (int i = 0; i < 8; i++) acc[i] *= dr;
            if (outf) {
#pragma unroll
                for (int i = 0; i < 8; i++) acc[i] = fmaxf(acc[i], 0.f);
                float4 o0 = make_float4(acc[0], acc[1], acc[2], acc[3]);
                float4 o1 = make_float4(acc[4], acc[5], acc[6], acc[7]);
                float* op = outf + node * 64 + j * 8;
                *(float4*)op = o0;
                *(float4*)(op + 4) = o1;
            } else {
                __half2 hh[4];
#pragma unroll
                for (int t = 0; t < 4; t++)
                    hh[t] = __floats2half2_rn(acc[2 * t], acc[2 * t + 1]);
                uint4 pk;
                pk.x = *(unsigned int*)&hh[0]; pk.y = *(unsigned int*)&hh[1];
                pk.z = *(unsigned int*)&hh[2]; pk.w = *(unsigned int*)&hh[3];
                ((uint4*)outh)[node * 8 + j] = pk;
            }
        }
    }
}

// Decode v3: 8 lanes/edge, 2 edges per group per iter => MLP 4 LDG.128/lane.
// fp16 z rows (128B). fp32 accumulate, 3-shfl reduce per edge.
// Tail duty: re-zero g_ideg for the next replay.
__global__ void decode_kernel(const int* __restrict__ pos,
                              const int* __restrict__ neg, long long E,
                              const __half* __restrict__ Zh, float* __restrict__ out,
                              int* __restrict__ ideg, int n) {
    long long tid = (long long)blockIdx.x * blockDim.x + threadIdx.x;
    if (tid < n) ideg[tid] = 0;     // reset degrees for next replay

    int lane = threadIdx.x & 31;
    int grp = lane >> 3;            // 0..3
    int j = lane & 7;               // uint4 slot (row = 8 uint4 = 64 halves)
    long long warp0 = tid >> 5;
    long long nwarps = ((long long)gridDim.x * blockDim.x) >> 5;
    long long twoE = 2 * E;
    const uint4* Z8 = (const uint4*)Zh;

    for (long long w8 = warp0 * 8; w8 < twoE; w8 += nwarps * 8) {
        long long wA = w8 + grp;
        long long wB = w8 + 4 + grp;
        bool vA = wA < twoE;
        bool vB = wB < twoE;
        int aA = 0, bA = 0, aB = 0, bB = 0;
        if (vA) {
            if (wA < E) { aA = pos[wA]; bA = pos[E + wA]; }
            else        { aA = neg[wA - E]; bA = neg[wA]; }
        }
        if (vB) {
            if (wB < E) { aB = pos[wB]; bB = pos[E + wB]; }
            else        { aB = neg[wB - E]; bB = neg[wB]; }
        }
        uint4 u0 = Z8[(long long)aA * 8 + j];
        uint4 u1 = Z8[(long long)bA * 8 + j];
        uint4 u2 = Z8[(long long)aB * 8 + j];
        uint4 u3 = Z8[(long long)bB * 8 + j];

        const __half2 *pa = (const __half2*)&u0, *pb = (const __half2*)&u1;
        const __half2 *pc = (const __half2*)&u2, *pd = (const __half2*)&u3;
        float sA = 0.f, sB = 0.f;
#pragma unroll
        for (int t = 0; t < 4; t++) {
            float2 fa = __half22float2(pa[t]);
            float2 fb = __half22float2(pb[t]);
            float2 fc = __half22float2(pc[t]);
            float2 fd = __half22float2(pd[t]);
            sA += fa.x * fb.x + fa.y * fb.y;
            sB += fc.x * fd.x + fc.y * fd.y;
        }
        sA += __shfl_xor_sync(0xffffffffu, sA, 1);
        sA += __shfl_xor_sync(0xffffffffu, sA, 2);
        sA += __shfl_xor_sync(0xffffffffu, sA, 4);
        sB += __shfl_xor_sync(0xffffffffu, sB, 1);
        sB += __shfl_xor_sync(0xffffffffu, sB, 2);
        sB += __shfl_xor_sync(0xffffffffu, sB, 4);
        if (j == 0) {
            if (vA) out[wA] = sA;
            if (vB) out[wB] = sB;
        }
    }
}

extern "C" void kernel_launch(void* const* d_in, const int* in_sizes, int n_in,
                              void* d_out, int out_size) {
    const float* x   = (const float*)d_in[0];
    const void*  pos = d_in[1];
    const void*  neg = d_in[2];
    const float* W1  = (const float*)d_in[3];
    const float* b1  = (const float*)d_in[4];
    const float* W2  = (const float*)d_in[5];
    const float* b2  = (const float*)d_in[6];
    float* out = (float*)d_out;

    long long E = (long long)in_sizes[1] / 2;   // 1.6M
    int n = NN;
    int Fin = in_sizes[0] / n;                  // 256

    int *pos32, *neg32, *csr, *ideg, *offs, *cursor;
    float *dis, *acc1;
    __half *h, *t, *z;
    cudaGetSymbolAddress((void**)&pos32,  g_pos32);
    cudaGetSymbolAddress((void**)&neg32,  g_neg32);
    cudaGetSymbolAddress((void**)&csr,    g_csr);
    cudaGetSymbolAddress((void**)&ideg,   g_ideg);
    cudaGetSymbolAddress((void**)&offs,   g_offs);
    cudaGetSymbolAddress((void**)&cursor, g_cursor);
    cudaGetSymbolAddress((void**)&dis,    g_dis);
    cudaGetSymbolAddress((void**)&h,      g_h);
    cudaGetSymbolAddress((void**)&acc1,   g_acc1);
    cudaGetSymbolAddress((void**)&t,      g_t);
    cudaGetSymbolAddress((void**)&z,      g_z);

    detect_kernel<<<1, 64>>>((const unsigned int*)pos);

    convdeg_kernel<<<GS_BLOCKS, GS_THREADS>>>(pos, neg, pos32, neg32, ideg, 2 * E);
    scan_kernel<<<1, 1024>>>(ideg, offs, cursor, dis, n);
    fill_kernel<<<GS_BLOCKS, GS_THREADS>>>(pos32, E, cursor, csr);

    int gblocks = (n + 255) / 256;
    gemm_kernel<<<gblocks, 256>>>(x, W1, b1, dis, h, n, Fin);
    gather_kernel<<<GS_BLOCKS, GS_THREADS>>>(offs, csr, dis, h, acc1, (__half*)0, n);
    gemm_kernel<<<gblocks, 256>>>(acc1, W2, b2, dis, t, n, 64);
    gather_kernel<<<GS_BLOCKS, GS_THREADS>>>(offs, csr, dis, t, (float*)0, z, n);

    decode_kernel<<<GS_BLOCKS, GS_THREADS>>>(pos32, neg32, E, z, out, ideg, n);
}

// round 8
// speedup vs baseline: 2.0269x; 1.0043x over previous
#include <cuda_runtime.h>
#include <cuda_fp16.h>
#include <cstdint>

#define NN 100000
#define EMAX 1600000
#define GS_BLOCKS 2368          // 16 CTAs/SM * 148 SMs
#define GS_THREADS 256

// -------- scratch (static device globals; no runtime allocation) --------
__device__ __align__(16) int    g_pos32[2 * EMAX];
__device__ __align__(16) int    g_neg32[2 * EMAX];
__device__ __align__(16) int    g_csr[EMAX];       // neighbor col ids grouped by row
__device__ __align__(16) int    g_ideg[NN];        // zero-initialized at load; decode re-zeros
__device__ __align__(16) int    g_offs[NN + 1];
__device__ __align__(16) int    g_cursor[NN];
__device__ __align__(16) float  g_dis[NN];
__device__ __align__(16) __half g_h[NN * 64];      // fp16: dis[i]*(x@W1+b1)
__device__ __align__(16) float  g_acc1[NN * 64];   // fp32: relu(layer1 aggregated)
__device__ __align__(16) __half g_t[NN * 64];      // fp16: dis[i]*(acc1@W2+b2)
__device__ __align__(16) __half g_z[NN * 64];      // fp16 z (decode-only consumer)

// Convert both index arrays to int32 and count row degrees, one pass, grid-stride.
// Per-block int64/int32 detection: ids < 2^17, so int64 => odd 32-bit words all 0.
__global__ void convdeg_kernel(const unsigned int* __restrict__ pos,
                               const unsigned int* __restrict__ neg,
                               int* __restrict__ pos32, int* __restrict__ neg32,
                               int* __restrict__ ideg, long long twoE) {
    int myok = 1;
    if (threadIdx.x < 64 && pos[2 * threadIdx.x + 1] != 0u) myok = 0;
    int is64 = __syncthreads_and(myok);

    long long E = twoE >> 1;
    long long stride = (long long)gridDim.x * blockDim.x;
    if (is64) {
        const long long* p64 = (const long long*)pos;
        const long long* n64 = (const long long*)neg;
        for (long long i = (long long)blockIdx.x * blockDim.x + threadIdx.x;
             i < twoE; i += stride) {
            int pv = (int)p64[i];
            pos32[i] = pv;
            neg32[i] = (int)n64[i];
            if (i < E) atomicAdd(&ideg[pv], 1);
        }
    } else {
        const int* p32 = (const int*)pos;
        const int* n32 = (const int*)neg;
        for (long long i = (long long)blockIdx.x * blockDim.x + threadIdx.x;
             i < twoE; i += stride) {
            int pv = p32[i];
            pos32[i] = pv;
            neg32[i] = n32[i];
            if (i < E) atomicAdd(&ideg[pv], 1);
        }
    }
}

// Single-block exclusive scan over n=100k degrees; writes offs[0..n], cursor, dis.
__global__ void scan_kernel(const int* __restrict__ ideg, int* offs, int* cursor,
                            float* dis, int n) {
    __shared__ int part[1024];
    int tid = threadIdx.x;
    int per = (n + 1023) / 1024;
    int start = tid * per;
    int end = min(start + per, n);
    int s = 0;
    for (int i = start; i < end; i++) s += ideg[i];
    part[tid] = s;
    __syncthreads();
    for (int off = 1; off < 1024; off <<= 1) {
        int t2 = (tid >= off) ? part[tid - off] : 0;
        __syncthreads();
        part[tid] += t2;
        __syncthreads();
    }
    int run = part[tid] - s;   // exclusive base
    for (int i = start; i < end; i++) {
        int d = ideg[i];
        offs[i] = run;
        cursor[i] = run;
        dis[i] = (d > 0) ? rsqrtf((float)d) : 0.0f;
        run += d;
    }
    if (tid == 0) offs[n] = part[1023];
}

__global__ void fill_kernel(const int* __restrict__ pos, long long E,
                            int* cursor, int* csr) {
    long long stride = (long long)gridDim.x * blockDim.x;
    for (long long e = (long long)blockIdx.x * blockDim.x + threadIdx.x;
         e < E; e += stride) {
        int row = pos[e];
        int col = pos[E + e];
        int slot = atomicAdd(&cursor[row], 1);
        csr[slot] = col;
    }
}

// GEMM: Yh[row,:] = fp16( dis[row]*(X[row,:] @ W + b) ).
// 256 threads/block, 256-row x 64-col tile, thread = 4 rows x 16 cols (64 acc).
__global__ void __launch_bounds__(256, 2)
gemm_kernel(const float* __restrict__ X,
            const float* __restrict__ W,
            const float* __restrict__ bias,
            const float* __restrict__ dis,
            __half* __restrict__ Yh,
            int n, int K) {
    __shared__ float xs[16 * 256];   // [k][row] 16 KB
    __shared__ float Ws[16 * 64];    // [k][col] 4 KB

    int tid = threadIdx.x;
    int rg = tid >> 2;               // 0..63: row group (4 rows each)
    int cq = (tid & 3) * 16;         // col offset
    int row0 = blockIdx.x * 256;

    float acc[4][16];
#pragma unroll
    for (int r = 0; r < 4; r++)
#pragma unroll
        for (int c = 0; c < 16; c++) acc[r][c] = 0.0f;

    int myrow = row0 + tid;
    const float4* Xr = (const float4*)(X + (long long)myrow * K);
    bool rvalid = myrow < n;

    for (int kt = 0; kt < K; kt += 16) {
        float4 wv = ((const float4*)(W + (long long)kt * 64))[tid];
        float4 v0 = make_float4(0.f, 0.f, 0.f, 0.f), v1 = v0, v2 = v0, v3 = v0;
        if (rvalid) {
            int kb = kt >> 2;
            v0 = __ldg(Xr + kb + 0);
            v1 = __ldg(Xr + kb + 1);
            v2 = __ldg(Xr + kb + 2);
            v3 = __ldg(Xr + kb + 3);
        }
        __syncthreads();
        ((float4*)Ws)[tid] = wv;
        xs[ 0 * 256 + tid] = v0.x; xs[ 1 * 256 + tid] = v0.y;
        xs[ 2 * 256 + tid] = v0.z; xs[ 3 * 256 + tid] = v0.w;
        xs[ 4 * 256 + tid] = v1.x; xs[ 5 * 256 + tid] = v1.y;
        xs[ 6 * 256 + tid] = v1.z; xs[ 7 * 256 + tid] = v1.w;
        xs[ 8 * 256 + tid] = v2.x; xs[ 9 * 256 + tid] = v2.y;
        xs[10 * 256 + tid] = v2.z; xs[11 * 256 + tid] = v2.w;
        xs[12 * 256 + tid] = v3.x; xs[13 * 256 + tid] = v3.y;
        xs[14 * 256 + tid] = v3.z; xs[15 * 256 + tid] = v3.w;
        __syncthreads();

#pragma unroll
        for (int k = 0; k < 16; k++) {
            float4 xv = *(const float4*)(xs + k * 256 + rg * 4);
            const float4* wr = (const float4*)(Ws + k * 64 + cq);
            float4 w0 = wr[0], w1 = wr[1], w2 = wr[2], w3 = wr[3];
            float wf[16] = {w0.x, w0.y, w0.z, w0.w, w1.x, w1.y, w1.z, w1.w,
                            w2.x, w2.y, w2.z, w2.w, w3.x, w3.y, w3.z, w3.w};
            float xf[4] = {xv.x, xv.y, xv.z, xv.w};
#pragma unroll
            for (int r = 0; r < 4; r++)
#pragma unroll
                for (int c = 0; c < 16; c++)
                    acc[r][c] += xf[r] * wf[c];
        }
    }

#pragma unroll
    for (int r = 0; r < 4; r++) {
        int row = row0 + rg * 4 + r;
        if (row < n) {
            float dr = dis[row];
            float o[16];
#pragma unroll
            for (int c = 0; c < 16; c++)
                o[c] = (acc[r][c] + bias[cq + c]) * dr;
            __half2 hh[8];
#pragma unroll
            for (int t = 0; t < 8; t++)
                hh[t] = __floats2half2_rn(o[2 * t], o[2 * t + 1]);
            uint4 pk0, pk1;
            pk0.x = *(unsigned int*)&hh[0]; pk0.y = *(unsigned int*)&hh[1];
            pk0.z = *(unsigned int*)&hh[2]; pk0.w = *(unsigned int*)&hh[3];
            pk1.x = *(unsigned int*)&hh[4]; pk1.y = *(unsigned int*)&hh[5];
            pk1.z = *(unsigned int*)&hh[6]; pk1.w = *(unsigned int*)&hh[7];
            __half* yp = Yh + (long long)row * 64 + cq;
            *(uint4*)yp = pk0;
            *(uint4*)(yp + 8) = pk1;
        }
    }
}

__device__ __forceinline__ void fmau4(float acc[8], uint4 u, float w) {
    const __half2* p = (const __half2*)&u;
#pragma unroll
    for (int t = 0; t < 4; t++) {
        float2 f = __half22float2(p[t]);
        acc[2 * t]     += w * f.x;
        acc[2 * t + 1] += w * f.y;
    }
}

// Gather v4: warp per node, quarter-warp (8 lanes) per neighbor, fp16 rows
// (128B = 8 uint4). Single clamped main loop: ALWAYS 4 independent loads per
// lane per iteration (indices clamped to e-1, weight 0/1 via FFMA) => MLP 4
// even for degree < 16. fp32 accumulate.
__global__ void gather_kernel(const int* __restrict__ offs,
                              const int* __restrict__ csr,
                              const float* __restrict__ dis,
                              const __half* __restrict__ H,
                              float* __restrict__ outf,      // layer-1 output (or null)
                              __half* __restrict__ outh,     // layer-2 fp16 z (or null)
                              int n) {
    int lane = threadIdx.x & 31;
    int q = lane >> 3;           // quarter 0..3
    int j = lane & 7;            // uint4 slot within the 64-half row
    long long warp0 = ((long long)blockIdx.x * blockDim.x + threadIdx.x) >> 5;
    long long nwarps = ((long long)gridDim.x * blockDim.x) >> 5;
    const uint4* H8 = (const uint4*)H;

    for (long long node = warp0; node < n; node += nwarps) {
        int s = offs[node];
        int e = offs[node + 1];
        float acc[8];
#pragma unroll
        for (int i = 0; i < 8; i++) acc[i] = 0.0f;

        for (int base = s; base < e; base += 16) {
            int i0 = base + 0 + q;
            int i1 = base + 4 + q;
            int i2 = base + 8 + q;
            int i3 = base + 12 + q;
            float w0 = (i0 < e) ? 1.f : 0.f;
            float w1 = (i1 < e) ? 1.f : 0.f;
            float w2 = (i2 < e) ? 1.f : 0.f;
            float w3 = (i3 < e) ? 1.f : 0.f;
            int last = e - 1;
            int c0 = csr[min(i0, last)];
            int c1 = csr[min(i1, last)];
            int c2 = csr[min(i2, last)];
            int c3 = csr[min(i3, last)];
            uint4 u0 = H8[(long long)c0 * 8 + j];
            uint4 u1 = H8[(long long)c1 * 8 + j];
            uint4 u2 = H8[(long long)c2 * 8 + j];
            uint4 u3 = H8[(long long)c3 * 8 + j];
            fmau4(acc, u0, w0);
            fmau4(acc, u1, w1);
            fmau4(acc, u2, w2);
            fmau4(acc, u3, w3);
        }

        // combine the 4 quarters
#pragma unroll
        for (int i = 0; i < 8; i++) {
            acc[i] += __shfl_xor_sync(0xffffffffu, acc[i], 8);
            acc[i] += __shfl_xor_sync(0xffffffffu, acc[i], 16);
        }

        if (q == 0) {
            float dr = dis[node];
#pragma unroll
            for (int i = 0; i < 8; i++) acc[i] *= dr;
            if (outf) {
#pragma unroll
                for (int i = 0; i < 8; i++) acc[i] = fmaxf(acc[i], 0.f);
                float4 o0 = make_float4(acc[0], acc[1], acc[2], acc[3]);
                float4 o1 = make_float4(acc[4], acc[5], acc[6], acc[7]);
                float* op = outf + node * 64 + j * 8;
                *(float4*)op = o0;
                *(float4*)(op + 4) = o1;
            } else {
                __half2 hh[4];
#pragma unroll
                for (int t = 0; t < 4; t++)
                    hh[t] = __floats2half2_rn(acc[2 * t], acc[2 * t + 1]);
                uint4 pk;
                pk.x = *(unsigned int*)&hh[0]; pk.y = *(unsigned int*)&hh[1];
                pk.z = *(unsigned int*)&hh[2]; pk.w = *(unsigned int*)&hh[3];
                ((uint4*)outh)[node * 8 + j] = pk;
            }
        }
    }
}

// Decode v4: 8 lanes/edge, 4 edges per group per iter => 8 independent
// LDG.128 per lane in flight. fp16 z rows (128B). fp32 accumulate.
// Tail duty: re-zero g_ideg for the next replay.
__global__ void decode_kernel(const int* __restrict__ pos,
                              const int* __restrict__ neg, long long E,
                              const __half* __restrict__ Zh, float* __restrict__ out,
                              int* __restrict__ ideg, int n) {
    long long tid = (long long)blockIdx.x * blockDim.x + threadIdx.x;
    if (tid < n) ideg[tid] = 0;     // reset degrees for next replay

    int lane = threadIdx.x & 31;
    int grp = lane >> 3;            // 0..3
    int j = lane & 7;               // uint4 slot (row = 8 uint4 = 64 halves)
    long long warp0 = tid >> 5;
    long long nwarps = ((long long)gridDim.x * blockDim.x) >> 5;
    long long twoE = 2 * E;
    const uint4* Z8 = (const uint4*)Zh;

    for (long long w16 = warp0 * 16; w16 < twoE; w16 += nwarps * 16) {
        long long wid[4];
        bool v[4];
        uint4 ua[4], ub[4];
#pragma unroll
        for (int u = 0; u < 4; u++) {
            long long w = w16 + 4 * u + grp;
            v[u] = w < twoE;
            wid[u] = w;
            long long wc = v[u] ? w : 0;
            int a, b;
            if (wc < E) { a = pos[wc];     b = pos[E + wc]; }
            else        { a = neg[wc - E]; b = neg[wc]; }
            ua[u] = Z8[(long long)a * 8 + j];
            ub[u] = Z8[(long long)b * 8 + j];
        }
#pragma unroll
        for (int u = 0; u < 4; u++) {
            const __half2* pa = (const __half2*)&ua[u];
            const __half2* pb = (const __half2*)&ub[u];
            float s = 0.f;
#pragma unroll
            for (int t = 0; t < 4; t++) {
                float2 fa = __half22float2(pa[t]);
                float2 fb = __half22float2(pb[t]);
                s += fa.x * fb.x + fa.y * fb.y;
            }
            s += __shfl_xor_sync(0xffffffffu, s, 1);
            s += __shfl_xor_sync(0xffffffffu, s, 2);
            s += __shfl_xor_sync(0xffffffffu, s, 4);
            if (j == 0 && v[u]) out[wid[u]] = s;
        }
    }
}

extern "C" void kernel_launch(void* const* d_in, const int* in_sizes, int n_in,
                              void* d_out, int out_size) {
    const float* x   = (const float*)d_in[0];
    const void*  pos = d_in[1];
    const void*  neg = d_in[2];
    const float* W1  = (const float*)d_in[3];
    const float* b1  = (const float*)d_in[4];
    const float* W2  = (const float*)d_in[5];
    const float* b2  = (const float*)d_in[6];
    float* out = (float*)d_out;

    long long E = (long long)in_sizes[1] / 2;   // 1.6M
    int n = NN;
    int Fin = in_sizes[0] / n;                  // 256

    int *pos32, *neg32, *csr, *ideg, *offs, *cursor;
    float *dis, *acc1;
    __half *h, *t, *z;
    cudaGetSymbolAddress((void**)&pos32,  g_pos32);
    cudaGetSymbolAddress((void**)&neg32,  g_neg32);
    cudaGetSymbolAddress((void**)&csr,    g_csr);
    cudaGetSymbolAddress((void**)&ideg,   g_ideg);
    cudaGetSymbolAddress((void**)&offs,   g_offs);
    cudaGetSymbolAddress((void**)&cursor, g_cursor);
    cudaGetSymbolAddress((void**)&dis,    g_dis);
    cudaGetSymbolAddress((void**)&h,      g_h);
    cudaGetSymbolAddress((void**)&acc1,   g_acc1);
    cudaGetSymbolAddress((void**)&t,      g_t);
    cudaGetSymbolAddress((void**)&z,      g_z);

    convdeg_kernel<<<GS_BLOCKS, GS_THREADS>>>((const unsigned int*)pos,
                                              (const unsigned int*)neg,
                                              pos32, neg32, ideg, 2 * E);
    scan_kernel<<<1, 1024>>>(ideg, offs, cursor, dis, n);
    fill_kernel<<<GS_BLOCKS, GS_THREADS>>>(pos32, E, cursor, csr);

    int gblocks = (n + 255) / 256;
    gemm_kernel<<<gblocks, 256>>>(x, W1, b1, dis, h, n, Fin);
    gather_kernel<<<GS_BLOCKS, GS_THREADS>>>(offs, csr, dis, h, acc1, (__half*)0, n);
    gemm_kernel<<<gblocks, 256>>>(acc1, W2, b2, dis, t, n, 64);
    gather_kernel<<<GS_BLOCKS, GS_THREADS>>>(offs, csr, dis, t, (float*)0, z, n);

    decode_kernel<<<GS_BLOCKS, GS_THREADS>>>(pos32, neg32, E, z, out, ideg, n);
}

// round 9
// speedup vs baseline: 2.5809x; 1.2733x over previous
#include <cuda_runtime.h>
#include <cuda_fp16.h>
#include <cstdint>

#define NN 100000
#define EMAX 1600000
#define GS_BLOCKS 2368          // 16 CTAs/SM * 148 SMs
#define GS_THREADS 256

// -------- scratch (static device globals; no runtime allocation) --------
__device__ __align__(16) int    g_pos32[2 * EMAX];
__device__ __align__(16) int    g_neg32[2 * EMAX];
__device__ __align__(16) int    g_csr[EMAX];       // neighbor col ids grouped by row
__device__ __align__(16) int    g_ideg[NN];        // zero-initialized at load; decode re-zeros
__device__ __align__(16) int    g_offs[NN + 1];
__device__ __align__(16) int    g_cursor[NN];
__device__ __align__(16) float  g_dis[NN];
__device__ __align__(16) __half g_h[NN * 64];      // fp16: dis[i]*(x@W1+b1)
__device__ __align__(16) __half g_acc1[NN * 64];   // fp16: relu(layer1 aggregated)
__device__ __align__(16) __half g_t[NN * 64];      // fp16: dis[i]*(acc1@W2+b2)
__device__ __align__(16) __half g_z[NN * 64];      // fp16 z (decode-only consumer)

// Convert both index arrays to int32 and count row degrees, one pass, grid-stride.
// Per-block int64/int32 detection: ids < 2^17, so int64 => odd 32-bit words all 0.
__global__ void convdeg_kernel(const unsigned int* __restrict__ pos,
                               const unsigned int* __restrict__ neg,
                               int* __restrict__ pos32, int* __restrict__ neg32,
                               int* __restrict__ ideg, long long twoE) {
    int myok = 1;
    if (threadIdx.x < 64 && pos[2 * threadIdx.x + 1] != 0u) myok = 0;
    int is64 = __syncthreads_and(myok);

    long long E = twoE >> 1;
    long long stride = (long long)gridDim.x * blockDim.x;
    if (is64) {
        const long long* p64 = (const long long*)pos;
        const long long* n64 = (const long long*)neg;
        for (long long i = (long long)blockIdx.x * blockDim.x + threadIdx.x;
             i < twoE; i += stride) {
            int pv = (int)p64[i];
            pos32[i] = pv;
            neg32[i] = (int)n64[i];
            if (i < E) atomicAdd(&ideg[pv], 1);
        }
    } else {
        const int* p32 = (const int*)pos;
        const int* n32 = (const int*)neg;
        for (long long i = (long long)blockIdx.x * blockDim.x + threadIdx.x;
             i < twoE; i += stride) {
            int pv = p32[i];
            pos32[i] = pv;
            neg32[i] = n32[i];
            if (i < E) atomicAdd(&ideg[pv], 1);
        }
    }
}

// Single-block exclusive scan over n=100k degrees; writes offs[0..n], cursor, dis.
__global__ void scan_kernel(const int* __restrict__ ideg, int* offs, int* cursor,
                            float* dis, int n) {
    __shared__ int part[1024];
    int tid = threadIdx.x;
    int per = (n + 1023) / 1024;
    int start = tid * per;
    int end = min(start + per, n);
    int s = 0;
    for (int i = start; i < end; i++) s += ideg[i];
    part[tid] = s;
    __syncthreads();
    for (int off = 1; off < 1024; off <<= 1) {
        int t2 = (tid >= off) ? part[tid - off] : 0;
        __syncthreads();
        part[tid] += t2;
        __syncthreads();
    }
    int run = part[tid] - s;   // exclusive base
    for (int i = start; i < end; i++) {
        int d = ideg[i];
        offs[i] = run;
        cursor[i] = run;
        dis[i] = (d > 0) ? rsqrtf((float)d) : 0.0f;
        run += d;
    }
    if (tid == 0) offs[n] = part[1023];
}

__global__ void fill_kernel(const int* __restrict__ pos, long long E,
                            int* cursor, int* csr) {
    long long stride = (long long)gridDim.x * blockDim.x;
    for (long long e = (long long)blockIdx.x * blockDim.x + threadIdx.x;
         e < E; e += stride) {
        int row = pos[e];
        int col = pos[E + e];
        int slot = atomicAdd(&cursor[row], 1);
        csr[slot] = col;
    }
}

// ---------------- tensor-core GEMM ----------------
#define SWZ(b) ((b) ^ (((b) >> 3) & 0x70))

__device__ __forceinline__ uint32_t smem_u32(const void* p) {
    return (uint32_t)__cvta_generic_to_shared(p);
}
__device__ __forceinline__ void ldsm4(uint32_t& r0, uint32_t& r1,
                                      uint32_t& r2, uint32_t& r3, uint32_t a) {
    asm volatile("ldmatrix.sync.aligned.m8n8.x4.shared.b16 {%0,%1,%2,%3}, [%4];"
                 : "=r"(r0), "=r"(r1), "=r"(r2), "=r"(r3) : "r"(a));
}
__device__ __forceinline__ void ldsm4t(uint32_t& r0, uint32_t& r1,
                                       uint32_t& r2, uint32_t& r3, uint32_t a) {
    asm volatile("ldmatrix.sync.aligned.m8n8.x4.trans.shared.b16 {%0,%1,%2,%3}, [%4];"
                 : "=r"(r0), "=r"(r1), "=r"(r2), "=r"(r3) : "r"(a));
}
__device__ __forceinline__ void mma16816(float* d,
                                         uint32_t a0, uint32_t a1, uint32_t a2, uint32_t a3,
                                         uint32_t b0, uint32_t b1) {
    asm volatile("mma.sync.aligned.m16n8k16.row.col.f32.f16.f16.f32 "
                 "{%0,%1,%2,%3}, {%4,%5,%6,%7}, {%8,%9}, {%0,%1,%2,%3};"
                 : "+f"(d[0]), "+f"(d[1]), "+f"(d[2]), "+f"(d[3])
                 : "r"(a0), "r"(a1), "r"(a2), "r"(a3), "r"(b0), "r"(b1));
}

__device__ __forceinline__ uint32_t packh2(float a, float b) {
    __half2 h = __floats2half2_rn(a, b);
    return *(uint32_t*)&h;
}

// Yh[row,:64] = fp16( dis[row] * (X[row,:K] @ W[K,64] + b) ).
// CTA: 256 threads (8 warps), tile 128 rows x 64 cols, K-chunks of 64.
// Warp w computes rows 16w..16w+15 via mma.sync m16n8k16 (fp16 in, fp32 acc).
__global__ void __launch_bounds__(256, 2)
gemm_mma_kernel(const void* __restrict__ Xv, int xIsHalf,
                const float* __restrict__ W,
                const float* __restrict__ bias,
                const float* __restrict__ dis,
                __half* __restrict__ Yh,
                int n, int K) {
    __shared__ __align__(16) __half xs[128 * 64];  // [row][k] swizzled, 16 KB
    __shared__ __align__(16) __half Ws[64 * 64];   // [k][n]  swizzled,  8 KB

    int t = threadIdx.x;
    int warp = t >> 5;
    int lane = t & 31;
    int row0 = blockIdx.x * 128;

    float acc[8][4];
#pragma unroll
    for (int f = 0; f < 8; f++)
#pragma unroll
        for (int i = 0; i < 4; i++) acc[f][i] = 0.0f;

    uint32_t xs_base = smem_u32(xs);
    uint32_t ws_base = smem_u32(Ws);

    // staging coords
    int srow = t >> 1;            // 0..127
    int kh = (t & 1) * 32;        // half-row of 32 k-values
    int grow = row0 + srow;
    int wk = t >> 2;              // 0..63 (W k-row)
    int nh = (t & 3) * 16;        // 16 n-values

    int nchunks = K >> 6;
    for (int kb = 0; kb < nchunks; kb++) {
        int kbase = kb * 64;

        // ---- load from global into registers ----
        uint4 pk[4];
        if (grow < n) {
            if (xIsHalf) {
                const uint4* Xr = (const uint4*)((const __half*)Xv +
                                   (long long)grow * K + kbase + kh);
#pragma unroll
                for (int i = 0; i < 4; i++) pk[i] = __ldg(Xr + i);
            } else {
                const float4* Xr = (const float4*)((const float*)Xv +
                                    (long long)grow * K + kbase + kh);
#pragma unroll
                for (int i = 0; i < 4; i++) {
                    float4 f0 = __ldg(Xr + 2 * i);
                    float4 f1 = __ldg(Xr + 2 * i + 1);
                    pk[i].x = packh2(f0.x, f0.y);
                    pk[i].y = packh2(f0.z, f0.w);
                    pk[i].z = packh2(f1.x, f1.y);
                    pk[i].w = packh2(f1.z, f1.w);
                }
            }
        } else {
            pk[0] = pk[1] = pk[2] = pk[3] = make_uint4(0, 0, 0, 0);
        }
        uint4 wpk[2];
        {
            const float4* Wr = (const float4*)(W + (long long)(kbase + wk) * 64 + nh);
#pragma unroll
            for (int i = 0; i < 2; i++) {
                float4 f0 = __ldg(Wr + 2 * i);
                float4 f1 = __ldg(Wr + 2 * i + 1);
                wpk[i].x = packh2(f0.x, f0.y);
                wpk[i].y = packh2(f0.z, f0.w);
                wpk[i].z = packh2(f1.x, f1.y);
                wpk[i].w = packh2(f1.z, f1.w);
            }
        }

        __syncthreads();   // previous chunk's compute done
#pragma unroll
        for (int i = 0; i < 4; i++)
            *(uint4*)((char*)xs + SWZ(srow * 128 + kh * 2 + 16 * i)) = pk[i];
#pragma unroll
        for (int i = 0; i < 2; i++)
            *(uint4*)((char*)Ws + SWZ(wk * 128 + nh * 2 + 16 * i)) = wpk[i];
        __syncthreads();

        // ---- compute: 4 k16 steps ----
        int arow = warp * 16 + (lane & 15);
        int acol = (lane >> 4) * 8;
#pragma unroll
        for (int s = 0; s < 4; s++) {
            uint32_t a0, a1, a2, a3;
            ldsm4(a0, a1, a2, a3,
                  xs_base + SWZ(arow * 128 + (s * 16 + acol) * 2));
            int brow = s * 16 + (lane & 15);
            int bcol = (lane >> 4) * 8;
#pragma unroll
            for (int i = 0; i < 4; i++) {
                uint32_t b0, b1, b2, b3;
                ldsm4t(b0, b1, b2, b3,
                       ws_base + SWZ(brow * 128 + (i * 16 + bcol) * 2));
                mma16816(acc[2 * i],     a0, a1, a2, a3, b0, b1);
                mma16816(acc[2 * i + 1], a0, a1, a2, a3, b2, b3);
            }
        }
        __syncthreads();   // compute done before next staging overwrites
    }

    // ---- epilogue: bias + dis scale, fp16 store ----
    int g = lane >> 2;
    int tig = lane & 3;
    int rowA = row0 + warp * 16 + g;
    int rowB = rowA + 8;
    float dA = (rowA < n) ? dis[rowA] : 0.0f;
    float dB = (rowB < n) ? dis[rowB] : 0.0f;
#pragma unroll
    for (int f = 0; f < 8; f++) {
        int c = f * 8 + tig * 2;
        float bx = __ldg(bias + c);
        float by = __ldg(bias + c + 1);
        if (rowA < n) {
            __half2 o = __floats2half2_rn((acc[f][0] + bx) * dA,
                                          (acc[f][1] + by) * dA);
            *(__half2*)(Yh + (long long)rowA * 64 + c) = o;
        }
        if (rowB < n) {
            __half2 o = __floats2half2_rn((acc[f][2] + bx) * dB,
                                          (acc[f][3] + by) * dB);
            *(__half2*)(Yh + (long long)rowB * 64 + c) = o;
        }
    }
}

__device__ __forceinline__ void fmau4(float acc[8], uint4 u, float w) {
    const __half2* p = (const __half2*)&u;
#pragma unroll
    for (int t = 0; t < 4; t++) {
        float2 f = __half22float2(p[t]);
        acc[2 * t]     += w * f.x;
        acc[2 * t + 1] += w * f.y;
    }
}

// Gather: warp per node, quarter-warp (8 lanes) per neighbor, fp16 rows
// (128B = 8 uint4). Single clamped main loop: ALWAYS 4 independent loads per
// lane per iteration. fp32 accumulate; fp16 output (optional relu).
__global__ void gather_kernel(const int* __restrict__ offs,
                              const int* __restrict__ csr,
                              const float* __restrict__ dis,
                              const __half* __restrict__ H,
                              __half* __restrict__ out,
                              int n, int do_relu) {
    int lane = threadIdx.x & 31;
    int q = lane >> 3;           // quarter 0..3
    int j = lane & 7;            // uint4 slot within the 64-half row
    long long warp0 = ((long long)blockIdx.x * blockDim.x + threadIdx.x) >> 5;
    long long nwarps = ((long long)gridDim.x * blockDim.x) >> 5;
    const uint4* H8 = (const uint4*)H;

    for (long long node = warp0; node < n; node += nwarps) {
        int s = offs[node];
        int e = offs[node + 1];
        float acc[8];
#pragma unroll
        for (int i = 0; i < 8; i++) acc[i] = 0.0f;

        for (int base = s; base < e; base += 16) {
            int i0 = base + 0 + q;
            int i1 = base + 4 + q;
            int i2 = base + 8 + q;
            int i3 = base + 12 + q;
            float w0 = (i0 < e) ? 1.f : 0.f;
            float w1 = (i1 < e) ? 1.f : 0.f;
            float w2 = (i2 < e) ? 1.f : 0.f;
            float w3 = (i3 < e) ? 1.f : 0.f;
            int last = e - 1;
            int c0 = csr[min(i0, last)];
            int c1 = csr[min(i1, last)];
            int c2 = csr[min(i2, last)];
            int c3 = csr[min(i3, last)];
            uint4 u0 = H8[(long long)c0 * 8 + j];
            uint4 u1 = H8[(long long)c1 * 8 + j];
            uint4 u2 = H8[(long long)c2 * 8 + j];
            uint4 u3 = H8[(long long)c3 * 8 + j];
            fmau4(acc, u0, w0);
            fmau4(acc, u1, w1);
            fmau4(acc, u2, w2);
            fmau4(acc, u3, w3);
        }

        // combine the 4 quarters
#pragma unroll
        for (int i = 0; i < 8; i++) {
            acc[i] += __shfl_xor_sync(0xffffffffu, acc[i], 8);
            acc[i] += __shfl_xor_sync(0xffffffffu, acc[i], 16);
        }

        if (q == 0) {
            float dr = dis[node];
#pragma unroll
            for (int i = 0; i < 8; i++) acc[i] *= dr;
            if (do_relu) {
#pragma unroll
                for (int i = 0; i < 8; i++) acc[i] = fmaxf(acc[i], 0.f);
            }
            __half2 hh[4];
#pragma unroll
            for (int t = 0; t < 4; t++)
                hh[t] = __floats2half2_rn(acc[2 * t], acc[2 * t + 1]);
            uint4 pk;
            pk.x = *(unsigned int*)&hh[0]; pk.y = *(unsigned int*)&hh[1];
            pk.z = *(unsigned int*)&hh[2]; pk.w = *(unsigned int*)&hh[3];
            ((uint4*)out)[node * 8 + j] = pk;
        }
    }
}

// Decode: 8 lanes/edge, 4 edges per group per iter => 8 independent
// LDG.128 per lane in flight. fp16 z rows (128B). fp32 accumulate.
// Tail duty: re-zero g_ideg for the next replay.
__global__ void decode_kernel(const int* __restrict__ pos,
                              const int* __restrict__ neg, long long E,
                              const __half* __restrict__ Zh, float* __restrict__ out,
                              int* __restrict__ ideg, int n) {
    long long tid = (long long)blockIdx.x * blockDim.x + threadIdx.x;
    if (tid < n) ideg[tid] = 0;     // reset degrees for next replay

    int lane = threadIdx.x & 31;
    int grp = lane >> 3;            // 0..3
    int j = lane & 7;               // uint4 slot (row = 8 uint4 = 64 halves)
    long long warp0 = tid >> 5;
    long long nwarps = ((long long)gridDim.x * blockDim.x) >> 5;
    long long twoE = 2 * E;
    const uint4* Z8 = (const uint4*)Zh;

    for (long long w16 = warp0 * 16; w16 < twoE; w16 += nwarps * 16) {
        long long wid[4];
        bool v[4];
        uint4 ua[4], ub[4];
#pragma unroll
        for (int u = 0; u < 4; u++) {
            long long w = w16 + 4 * u + grp;
            v[u] = w < twoE;
            wid[u] = w;
            long long wc = v[u] ? w : 0;
            int a, b;
            if (wc < E) { a = pos[wc];     b = pos[E + wc]; }
            else        { a = neg[wc - E]; b = neg[wc]; }
            ua[u] = Z8[(long long)a * 8 + j];
            ub[u] = Z8[(long long)b * 8 + j];
        }
#pragma unroll
        for (int u = 0; u < 4; u++) {
            const __half2* pa = (const __half2*)&ua[u];
            const __half2* pb = (const __half2*)&ub[u];
            float s = 0.f;
#pragma unroll
            for (int t = 0; t < 4; t++) {
                float2 fa = __half22float2(pa[t]);
                float2 fb = __half22float2(pb[t]);
                s += fa.x * fb.x + fa.y * fb.y;
            }
            s += __shfl_xor_sync(0xffffffffu, s, 1);
            s += __shfl_xor_sync(0xffffffffu, s, 2);
            s += __shfl_xor_sync(0xffffffffu, s, 4);
            if (j == 0 && v[u]) out[wid[u]] = s;
        }
    }
}

extern "C" void kernel_launch(void* const* d_in, const int* in_sizes, int n_in,
                              void* d_out, int out_size) {
    const float* x   = (const float*)d_in[0];
    const void*  pos = d_in[1];
    const void*  neg = d_in[2];
    const float* W1  = (const float*)d_in[3];
    const float* b1  = (const float*)d_in[4];
    const float* W2  = (const float*)d_in[5];
    const float* b2  = (const float*)d_in[6];
    float* out = (float*)d_out;

    long long E = (long long)in_sizes[1] / 2;   // 1.6M
    int n = NN;
    int Fin = in_sizes[0] / n;                  // 256

    int *pos32, *neg32, *csr, *ideg, *offs, *cursor;
    float *dis;
    __half *h, *acc1, *t, *z;
    cudaGetSymbolAddress((void**)&pos32,  g_pos32);
    cudaGetSymbolAddress((void**)&neg32,  g_neg32);
    cudaGetSymbolAddress((void**)&csr,    g_csr);
    cudaGetSymbolAddress((void**)&ideg,   g_ideg);
    cudaGetSymbolAddress((void**)&offs,   g_offs);
    cudaGetSymbolAddress((void**)&cursor, g_cursor);
    cudaGetSymbolAddress((void**)&dis,    g_dis);
    cudaGetSymbolAddress((void**)&h,      g_h);
    cudaGetSymbolAddress((void**)&acc1,   g_acc1);
    cudaGetSymbolAddress((void**)&t,      g_t);
    cudaGetSymbolAddress((void**)&z,      g_z);

    convdeg_kernel<<<GS_BLOCKS, GS_THREADS>>>((const unsigned int*)pos,
                                              (const unsigned int*)neg,
                                              pos32, neg32, ideg, 2 * E);
    scan_kernel<<<1, 1024>>>(ideg, offs, cursor, dis, n);
    fill_kernel<<<GS_BLOCKS, GS_THREADS>>>(pos32, E, cursor, csr);

    int gblocks = (n + 127) / 128;
    gemm_mma_kernel<<<gblocks, 256>>>(x, 0, W1, b1, dis, h, n, Fin);
    gather_kernel<<<GS_BLOCKS, GS_THREADS>>>(offs, csr, dis, h, acc1, n, 1);
    gemm_mma_kernel<<<gblocks, 256>>>(acc1, 1, W2, b2, dis, t, n, 64);
    gather_kernel<<<GS_BLOCKS, GS_THREADS>>>(offs, csr, dis, t, z, n, 0);

    decode_kernel<<<GS_BLOCKS, GS_THREADS>>>(pos32, neg32, E, z, out, ideg, n);
}

// round 10
// speedup vs baseline: 2.6105x; 1.0114x over previous
#include <cuda_runtime.h>
#include <cuda_fp16.h>
#include <cstdint>

#define NN 100000
#define EMAX 1600000
#define GS_BLOCKS 2368          // 16 CTAs/SM * 148 SMs
#define GS_THREADS 256

// -------- scratch (static device globals; no runtime allocation) --------
__device__ __align__(16) int    g_pos32[2 * EMAX];
__device__ __align__(16) int    g_csr[EMAX];       // neighbor col ids grouped by row
__device__ __align__(16) int    g_ideg[NN];        // zero-initialized at load; decode re-zeros
__device__ __align__(16) int    g_offs[NN + 1];
__device__ __align__(16) int    g_cursor[NN];
__device__ __align__(16) float  g_dis[NN];
__device__ __align__(16) __half g_h[NN * 64];      // fp16: dis[i]*(x@W1+b1)
__device__ __align__(16) __half g_acc1[NN * 64];   // fp16: relu(layer1 aggregated)
__device__ __align__(16) __half g_t[NN * 64];      // fp16: dis[i]*(acc1@W2+b2)
__device__ __align__(16) __half g_z[NN * 64];      // fp16 z (decode-only consumer)
__device__ int g_is64;

// Convert pos to int32 + count row degrees, one pass, grid-stride.
// Per-block int64/int32 detection: ids < 2^17, so int64 => odd 32-bit words all 0.
// Publishes g_is64 for decode (all blocks compute the same value).
__global__ void convdeg_kernel(const unsigned int* __restrict__ pos,
                               int* __restrict__ pos32,
                               int* __restrict__ ideg, long long twoE) {
    int myok = 1;
    if (threadIdx.x < 64 && pos[2 * threadIdx.x + 1] != 0u) myok = 0;
    int is64 = __syncthreads_and(myok);
    if (threadIdx.x == 0 && blockIdx.x == 0) g_is64 = is64;

    long long E = twoE >> 1;
    long long stride = (long long)gridDim.x * blockDim.x;
    if (is64) {
        const long long* p64 = (const long long*)pos;
        for (long long i = (long long)blockIdx.x * blockDim.x + threadIdx.x;
             i < twoE; i += stride) {
            int pv = (int)p64[i];
            pos32[i] = pv;
            if (i < E) atomicAdd(&ideg[pv], 1);
        }
    } else {
        const int* p32 = (const int*)pos;
        for (long long i = (long long)blockIdx.x * blockDim.x + threadIdx.x;
             i < twoE; i += stride) {
            int pv = p32[i];
            pos32[i] = pv;
            if (i < E) atomicAdd(&ideg[pv], 1);
        }
    }
}

// Single-block exclusive scan over n=100k degrees; writes offs[0..n], cursor, dis.
__global__ void scan_kernel(const int* __restrict__ ideg, int* offs, int* cursor,
                            float* dis, int n) {
    __shared__ int part[1024];
    int tid = threadIdx.x;
    int per = (n + 1023) / 1024;
    int start = tid * per;
    int end = min(start + per, n);
    int s = 0;
    for (int i = start; i < end; i++) s += ideg[i];
    part[tid] = s;
    __syncthreads();
    for (int off = 1; off < 1024; off <<= 1) {
        int t2 = (tid >= off) ? part[tid - off] : 0;
        __syncthreads();
        part[tid] += t2;
        __syncthreads();
    }
    int run = part[tid] - s;   // exclusive base
    for (int i = start; i < end; i++) {
        int d = ideg[i];
        offs[i] = run;
        cursor[i] = run;
        dis[i] = (d > 0) ? rsqrtf((float)d) : 0.0f;
        run += d;
    }
    if (tid == 0) offs[n] = part[1023];
}

__global__ void fill_kernel(const int* __restrict__ pos, long long E,
                            int* cursor, int* csr) {
    long long stride = (long long)gridDim.x * blockDim.x;
    for (long long e = (long long)blockIdx.x * blockDim.x + threadIdx.x;
         e < E; e += stride) {
        int row = pos[e];
        int col = pos[E + e];
        int slot = atomicAdd(&cursor[row], 1);
        csr[slot] = col;
    }
}

// ---------------- tensor-core GEMM (double-buffered, K-chunk 32) ----------
#define SWZ(b)   ((b) ^ (((b) >> 3) & 0x70))   // 128B rows
#define SWZ64(b) ((b) ^ (((b) >> 3) & 0x30))   // 64B rows

__device__ __forceinline__ uint32_t smem_u32(const void* p) {
    return (uint32_t)__cvta_generic_to_shared(p);
}
__device__ __forceinline__ void ldsm4(uint32_t& r0, uint32_t& r1,
                                      uint32_t& r2, uint32_t& r3, uint32_t a) {
    asm volatile("ldmatrix.sync.aligned.m8n8.x4.shared.b16 {%0,%1,%2,%3}, [%4];"
                 : "=r"(r0), "=r"(r1), "=r"(r2), "=r"(r3) : "r"(a));
}
__device__ __forceinline__ void ldsm4t(uint32_t& r0, uint32_t& r1,
                                       uint32_t& r2, uint32_t& r3, uint32_t a) {
    asm volatile("ldmatrix.sync.aligned.m8n8.x4.trans.shared.b16 {%0,%1,%2,%3}, [%4];"
                 : "=r"(r0), "=r"(r1), "=r"(r2), "=r"(r3) : "r"(a));
}
__device__ __forceinline__ void mma16816(float* d,
                                         uint32_t a0, uint32_t a1, uint32_t a2, uint32_t a3,
                                         uint32_t b0, uint32_t b1) {
    asm volatile("mma.sync.aligned.m16n8k16.row.col.f32.f16.f16.f32 "
                 "{%0,%1,%2,%3}, {%4,%5,%6,%7}, {%8,%9}, {%0,%1,%2,%3};"
                 : "+f"(d[0]), "+f"(d[1]), "+f"(d[2]), "+f"(d[3])
                 : "r"(a0), "r"(a1), "r"(a2), "r"(a3), "r"(b0), "r"(b1));
}
__device__ __forceinline__ uint32_t packh2(float a, float b) {
    __half2 h = __floats2half2_rn(a, b);
    return *(uint32_t*)&h;
}

// Yh[row,:64] = fp16( dis[row] * (X[row,:K] @ W[K,64] + b) ).
// CTA: 256 threads (8 warps), tile 128 rows x 64 cols, K-chunk 32,
// double-buffered smem: LDGs for chunk k+1 in flight while computing chunk k.
__global__ void __launch_bounds__(256, 2)
gemm_mma_kernel(const void* __restrict__ Xv, int xIsHalf,
                const float* __restrict__ W,
                const float* __restrict__ bias,
                const float* __restrict__ dis,
                __half* __restrict__ Yh,
                int n, int K) {
    __shared__ __align__(16) __half xs[2][128 * 32];  // 2 x 8 KB  [row][k] SW64
    __shared__ __align__(16) __half Ws[2][32 * 64];   // 2 x 4 KB  [k][n]   SW128

    int t = threadIdx.x;
    int warp = t >> 5;
    int lane = t & 31;
    int row0 = blockIdx.x * 128;

    float acc[8][4];
#pragma unroll
    for (int f = 0; f < 8; f++)
#pragma unroll
        for (int i = 0; i < 4; i++) acc[f][i] = 0.0f;

    // staging coords
    int srow = t >> 1;            // 0..127
    int kh = (t & 1) * 16;        // 16 k-values per thread
    int grow = row0 + srow;
    bool rvalid = grow < n;
    int wk = t >> 3;              // 0..31 (W k-row)
    int nh = (t & 7) * 8;         // 8 n-values

    uint32_t xs_b[2] = { smem_u32(xs[0]), smem_u32(xs[1]) };
    uint32_t ws_b[2] = { smem_u32(Ws[0]), smem_u32(Ws[1]) };

    int nchunks = K >> 5;
    uint4 pk0, pk1, wpk;

    // ---- chunk loader into registers ----
    auto load_chunk = [&](int kb) {
        int kbase = kb * 32;
        if (rvalid) {
            if (xIsHalf) {
                const uint4* Xr = (const uint4*)((const __half*)Xv +
                                   (long long)grow * K + kbase + kh);
                pk0 = __ldg(Xr);
                pk1 = __ldg(Xr + 1);
            } else {
                const float4* Xr = (const float4*)((const float*)Xv +
                                    (long long)grow * K + kbase + kh);
                float4 f0 = __ldg(Xr + 0), f1 = __ldg(Xr + 1);
                float4 f2 = __ldg(Xr + 2), f3 = __ldg(Xr + 3);
                pk0.x = packh2(f0.x, f0.y); pk0.y = packh2(f0.z, f0.w);
                pk0.z = packh2(f1.x, f1.y); pk0.w = packh2(f1.z, f1.w);
                pk1.x = packh2(f2.x, f2.y); pk1.y = packh2(f2.z, f2.w);
                pk1.z = packh2(f3.x, f3.y); pk1.w = packh2(f3.z, f3.w);
            }
        } else {
            pk0 = pk1 = make_uint4(0, 0, 0, 0);
        }
        const float4* Wr = (const float4*)(W + (long long)(kbase + wk) * 64 + nh);
        float4 g0 = __ldg(Wr), g1 = __ldg(Wr + 1);
        wpk.x = packh2(g0.x, g0.y); wpk.y = packh2(g0.z, g0.w);
        wpk.z = packh2(g1.x, g1.y); wpk.w = packh2(g1.z, g1.w);
    };
    auto store_chunk = [&](int buf) {
        *(uint4*)((char*)xs[buf] + SWZ64(srow * 64 + kh * 2)) = pk0;
        *(uint4*)((char*)xs[buf] + SWZ64(srow * 64 + kh * 2 + 16)) = pk1;
        *(uint4*)((char*)Ws[buf] + SWZ(wk * 128 + nh * 2)) = wpk;
    };

    load_chunk(0);
    store_chunk(0);

    int arow = warp * 16 + (lane & 15);
    int acol = (lane >> 4) * 8;
    int brl = lane & 15;
    int bcol = (lane >> 4) * 8;

    for (int kb = 0; kb < nchunks; kb++) {
        int cur = kb & 1;
        if (kb + 1 < nchunks) load_chunk(kb + 1);   // LDGs in flight
        __syncthreads();                            // buf[cur] visible

        // ---- compute: 2 k16 steps from buf[cur] ----
#pragma unroll
        for (int s = 0; s < 2; s++) {
            uint32_t a0, a1, a2, a3;
            ldsm4(a0, a1, a2, a3,
                  xs_b[cur] + SWZ64(arow * 64 + (s * 16 + acol) * 2));
            int brow = s * 16 + brl;
#pragma unroll
            for (int i = 0; i < 4; i++) {
                uint32_t b0, b1, b2, b3;
                ldsm4t(b0, b1, b2, b3,
                       ws_b[cur] + SWZ(brow * 128 + (i * 16 + bcol) * 2));
                mma16816(acc[2 * i],     a0, a1, a2, a3, b0, b1);
                mma16816(acc[2 * i + 1], a0, a1, a2, a3, b2, b3);
            }
        }
        if (kb + 1 < nchunks) store_chunk(cur ^ 1); // other buffer: no sync needed
    }

    // ---- epilogue: bias + dis scale, fp16 store ----
    int g = lane >> 2;
    int tig = lane & 3;
    int rowA = row0 + warp * 16 + g;
    int rowB = rowA + 8;
    float dA = (rowA < n) ? dis[rowA] : 0.0f;
    float dB = (rowB < n) ? dis[rowB] : 0.0f;
#pragma unroll
    for (int f = 0; f < 8; f++) {
        int c = f * 8 + tig * 2;
        float bx = __ldg(bias + c);
        float by = __ldg(bias + c + 1);
        if (rowA < n) {
            __half2 o = __floats2half2_rn((acc[f][0] + bx) * dA,
                                          (acc[f][1] + by) * dA);
            *(__half2*)(Yh + (long long)rowA * 64 + c) = o;
        }
        if (rowB < n) {
            __half2 o = __floats2half2_rn((acc[f][2] + bx) * dB,
                                          (acc[f][3] + by) * dB);
            *(__half2*)(Yh + (long long)rowB * 64 + c) = o;
        }
    }
}

__device__ __forceinline__ void fmau4(float acc[8], uint4 u, float w) {
    const __half2* p = (const __half2*)&u;
#pragma unroll
    for (int t = 0; t < 4; t++) {
        float2 f = __half22float2(p[t]);
        acc[2 * t]     += w * f.x;
        acc[2 * t + 1] += w * f.y;
    }
}

// Gather: warp per node, quarter-warp (8 lanes) per neighbor, fp16 rows
// (128B = 8 uint4). Clamped main loop: always 4 independent loads per lane
// per iteration. fp32 accumulate; fp16 output (optional relu).
__global__ void gather_kernel(const int* __restrict__ offs,
                              const int* __restrict__ csr,
                              const float* __restrict__ dis,
                              const __half* __restrict__ H,
                              __half* __restrict__ out,
                              int n, int do_relu) {
    int lane = threadIdx.x & 31;
    int q = lane >> 3;           // quarter 0..3
    int j = lane & 7;            // uint4 slot within the 64-half row
    long long warp0 = ((long long)blockIdx.x * blockDim.x + threadIdx.x) >> 5;
    long long nwarps = ((long long)gridDim.x * blockDim.x) >> 5;
    const uint4* H8 = (const uint4*)H;

    for (long long node = warp0; node < n; node += nwarps) {
        int s = offs[node];
        int e = offs[node + 1];
        float acc[8];
#pragma unroll
        for (int i = 0; i < 8; i++) acc[i] = 0.0f;

        for (int base = s; base < e; base += 16) {
            int i0 = base + 0 + q;
            int i1 = base + 4 + q;
            int i2 = base + 8 + q;
            int i3 = base + 12 + q;
            float w0 = (i0 < e) ? 1.f : 0.f;
            float w1 = (i1 < e) ? 1.f : 0.f;
            float w2 = (i2 < e) ? 1.f : 0.f;
            float w3 = (i3 < e) ? 1.f : 0.f;
            int last = e - 1;
            int c0 = csr[min(i0, last)];
            int c1 = csr[min(i1, last)];
            int c2 = csr[min(i2, last)];
            int c3 = csr[min(i3, last)];
            uint4 u0 = H8[(long long)c0 * 8 + j];
            uint4 u1 = H8[(long long)c1 * 8 + j];
            uint4 u2 = H8[(long long)c2 * 8 + j];
            uint4 u3 = H8[(long long)c3 * 8 + j];
            fmau4(acc, u0, w0);
            fmau4(acc, u1, w1);
            fmau4(acc, u2, w2);
            fmau4(acc, u3, w3);
        }

#pragma unroll
        for (int i = 0; i < 8; i++) {
            acc[i] += __shfl_xor_sync(0xffffffffu, acc[i], 8);
            acc[i] += __shfl_xor_sync(0xffffffffu, acc[i], 16);
        }

        if (q == 0) {
            float dr = dis[node];
#pragma unroll
            for (int i = 0; i < 8; i++) acc[i] *= dr;
            if (do_relu) {
#pragma unroll
                for (int i = 0; i < 8; i++) acc[i] = fmaxf(acc[i], 0.f);
            }
            __half2 hh[4];
#pragma unroll
            for (int t = 0; t < 4; t++)
                hh[t] = __floats2half2_rn(acc[2 * t], acc[2 * t + 1]);
            uint4 pk;
            pk.x = *(unsigned int*)&hh[0]; pk.y = *(unsigned int*)&hh[1];
            pk.z = *(unsigned int*)&hh[2]; pk.w = *(unsigned int*)&hh[3];
            ((uint4*)out)[node * 8 + j] = pk;
        }
    }
}

// Decode: 8 lanes/edge, 4 edges per group per iter => 8 independent LDG.128
// per lane in flight. Reads pos as int32, neg directly (dtype via g_is64).
// fp16 z rows (128B). fp32 accumulate. Tail duty: re-zero g_ideg.
__global__ void decode_kernel(const int* __restrict__ pos,
                              const void* __restrict__ negv, long long E,
                              const __half* __restrict__ Zh, float* __restrict__ out,
                              int* __restrict__ ideg, int n) {
    long long tid = (long long)blockIdx.x * blockDim.x + threadIdx.x;
    if (tid < n) ideg[tid] = 0;     // reset degrees for next replay

    int is64 = g_is64;
    const long long* n64 = (const long long*)negv;
    const int* n32 = (const int*)negv;

    int lane = threadIdx.x & 31;
    int grp = lane >> 3;            // 0..3
    int j = lane & 7;               // uint4 slot (row = 8 uint4 = 64 halves)
    long long warp0 = tid >> 5;
    long long nwarps = ((long long)gridDim.x * blockDim.x) >> 5;
    long long twoE = 2 * E;
    const uint4* Z8 = (const uint4*)Zh;

    for (long long w16 = warp0 * 16; w16 < twoE; w16 += nwarps * 16) {
        long long wid[4];
        bool v[4];
        uint4 ua[4], ub[4];
#pragma unroll
        for (int u = 0; u < 4; u++) {
            long long w = w16 + 4 * u + grp;
            v[u] = w < twoE;
            wid[u] = w;
            long long wc = v[u] ? w : 0;
            int a, b;
            if (wc < E) {
                a = pos[wc];
                b = pos[E + wc];
            } else if (is64) {
                a = (int)n64[wc - E];
                b = (int)n64[wc];
            } else {
                a = n32[wc - E];
                b = n32[wc];
            }
            ua[u] = Z8[(long long)a * 8 + j];
            ub[u] = Z8[(long long)b * 8 + j];
        }
#pragma unroll
        for (int u = 0; u < 4; u++) {
            const __half2* pa = (const __half2*)&ua[u];
            const __half2* pb = (const __half2*)&ub[u];
            float s = 0.f;
#pragma unroll
            for (int t = 0; t < 4; t++) {
                float2 fa = __half22float2(pa[t]);
                float2 fb = __half22float2(pb[t]);
                s += fa.x * fb.x + fa.y * fb.y;
            }
            s += __shfl_xor_sync(0xffffffffu, s, 1);
            s += __shfl_xor_sync(0xffffffffu, s, 2);
            s += __shfl_xor_sync(0xffffffffu, s, 4);
            if (j == 0 && v[u]) out[wid[u]] = s;
        }
    }
}

extern "C" void kernel_launch(void* const* d_in, const int* in_sizes, int n_in,
                              void* d_out, int out_size) {
    const float* x   = (const float*)d_in[0];
    const void*  pos = d_in[1];
    const void*  neg = d_in[2];
    const float* W1  = (const float*)d_in[3];
    const float* b1  = (const float*)d_in[4];
    const float* W2  = (const float*)d_in[5];
    const float* b2  = (const float*)d_in[6];
    float* out = (float*)d_out;

    long long E = (long long)in_sizes[1] / 2;   // 1.6M
    int n = NN;
    int Fin = in_sizes[0] / n;                  // 256

    int *pos32, *csr, *ideg, *offs, *cursor;
    float *dis;
    __half *h, *acc1, *t, *z;
    cudaGetSymbolAddress((void**)&pos32,  g_pos32);
    cudaGetSymbolAddress((void**)&csr,    g_csr);
    cudaGetSymbolAddress((void**)&ideg,   g_ideg);
    cudaGetSymbolAddress((void**)&offs,   g_offs);
    cudaGetSymbolAddress((void**)&cursor, g_cursor);
    cudaGetSymbolAddress((void**)&dis,    g_dis);
    cudaGetSymbolAddress((void**)&h,      g_h);
    cudaGetSymbolAddress((void**)&acc1,   g_acc1);
    cudaGetSymbolAddress((void**)&t,      g_t);
    cudaGetSymbolAddress((void**)&z,      g_z);

    convdeg_kernel<<<GS_BLOCKS, GS_THREADS>>>((const unsigned int*)pos,
                                              pos32, ideg, 2 * E);
    scan_kernel<<<1, 1024>>>(ideg, offs, cursor, dis, n);
    fill_kernel<<<GS_BLOCKS, GS_THREADS>>>(pos32, E, cursor, csr);

    int gblocks = (n + 127) / 128;
    gemm_mma_kernel<<<gblocks, 256>>>(x, 0, W1, b1, dis, h, n, Fin);
    gather_kernel<<<GS_BLOCKS, GS_THREADS>>>(offs, csr, dis, h, acc1, n, 1);
    gemm_mma_kernel<<<gblocks, 256>>>(acc1, 1, W2, b2, dis, t, n, 64);
    gather_kernel<<<GS_BLOCKS, GS_THREADS>>>(offs, csr, dis, t, z, n, 0);

    decode_kernel<<<GS_BLOCKS, GS_THREADS>>>(pos32, neg, E, z, out, ideg, n);
}